// round 8
// baseline (speedup 1.0000x reference)
#include <cuda_runtime.h>
#include <cuda_bf16.h>

#define NNODES 65536
#define NEDGES 524288
#define NGRAPH 128
#define NPG    512
#define EPG    4096
#define F_IN   128
#define H1D    64
#define H2D    128
#define NCLS   10
#define KSEL   410

typedef unsigned int U32;

// ---------------- scratch (static device globals; no allocation) -------------
__device__ __align__(16) int    g_cnt[NNODES];
__device__ __align__(16) int    g_fill[NNODES];
__device__ __align__(16) int    g_rowptr[NNODES];
__device__ __align__(16) float  g_dis[NNODES];
__device__ __align__(16) float2 g_csre[NEDGES];   // (bitcast src idx, edge weight)
__device__ __align__(16) float  g_h1[NNODES * H1D];
__device__ __align__(16) float  g_out1[NNODES * H1D];
__device__ __align__(16) float  g_h2[NNODES * H2D];
__device__ __align__(16) float  g_out2[NNODES * H2D];
__device__ __align__(16) float  g_score[NNODES];
__device__ int g_is64;

// ---------------- helpers ----------------------------------------------------
// Split fp32 -> (hi, lo) bf16 pair, packed 2-per-word (even k in low half).
__device__ __forceinline__ void split2(float vx, float vy, U32& whi, U32& wlo) {
    unsigned short h0 = __bfloat16_as_ushort(__float2bfloat16_rn(vx));
    unsigned short h1 = __bfloat16_as_ushort(__float2bfloat16_rn(vy));
    whi = (U32)h0 | ((U32)h1 << 16);
    float r0 = vx - __uint_as_float((U32)h0 << 16);
    float r1 = vy - __uint_as_float((U32)h1 << 16);
    unsigned short l0 = __bfloat16_as_ushort(__float2bfloat16_rn(r0));
    unsigned short l1 = __bfloat16_as_ushort(__float2bfloat16_rn(r1));
    wlo = (U32)l0 | ((U32)l1 << 16);
}

__device__ __forceinline__ void mma16816(float* c, const U32* a, U32 b0, U32 b1) {
    asm volatile(
        "mma.sync.aligned.m16n8k16.row.col.f32.bf16.bf16.f32 "
        "{%0,%1,%2,%3}, {%4,%5,%6,%7}, {%8,%9}, {%0,%1,%2,%3};"
        : "+f"(c[0]), "+f"(c[1]), "+f"(c[2]), "+f"(c[3])
        : "r"(a[0]), "r"(a[1]), "r"(a[2]), "r"(a[3]), "r"(b0), "r"(b1));
}

// ---------------- structure kernels ----------------------------------------
__global__ void zero_kernel() {
    int i = blockIdx.x * blockDim.x + threadIdx.x;
    g_cnt[i] = 0;
    g_fill[i] = 0;
}

// edge_index may arrive as int64 (x64 mode) or int32. Node ids < 2^16, so if
// int64 every odd 32-bit word of a prefix is 0.
__global__ void detect_kernel(const int* __restrict__ ei) {
    __shared__ int sred[256];
    int t = threadIdx.x;
    int v = 0;
    for (int i = t; i < 1024; i += 256) v |= ei[2 * i + 1];
    sred[t] = v;
    __syncthreads();
    for (int o = 128; o > 0; o >>= 1) {
        if (t < o) sred[t] |= sred[t + o];
        __syncthreads();
    }
    if (t == 0) g_is64 = (sred[0] == 0) ? 1 : 0;
}

__global__ void count_kernel(const int* __restrict__ ei) {
    int i = blockIdx.x * blockDim.x + threadIdx.x;
    int d = g_is64 ? ei[2 * (NEDGES + i)] : ei[NEDGES + i];
    atomicAdd(&g_cnt[d], 1);
}

__global__ void scan_kernel() {
    __shared__ int s[NPG];
    int b = blockIdx.x, t = threadIdx.x;
    int node = b * NPG + t;
    int c = g_cnt[node];
    s[t] = c;
    __syncthreads();
    for (int off = 1; off < NPG; off <<= 1) {
        int v = (t >= off) ? s[t - off] : 0;
        __syncthreads();
        s[t] += v;
        __syncthreads();
    }
    g_rowptr[node] = b * EPG + s[t] - c;
    g_dis[node] = rsqrtf((float)(c + 1));   // +1 self-loop
}

__global__ void scatter_kernel(const int* __restrict__ ei) {
    int i = blockIdx.x * blockDim.x + threadIdx.x;
    int sv, dv;
    if (g_is64) { sv = ei[2 * i]; dv = ei[2 * (NEDGES + i)]; }
    else        { sv = ei[i];     dv = ei[NEDGES + i]; }
    int p = atomicAdd(&g_fill[dv], 1);
    float w = g_dis[sv] * g_dis[dv];
    g_csre[g_rowptr[dv] + p] = make_float2(__int_as_float(sv), w);
}

// ---------------- GEMM 1: h1[65536,64] = x @ W1[128,64], bf16-split mma ------
// 512 thr, block tile 128x64, warp grid 4x4 (warp tile 32x16), K chunks of 16.
__global__ void __launch_bounds__(512) gemm1_kernel(const float* __restrict__ x,
                                                    const float* __restrict__ W) {
    __shared__ U32 sBhi[64 * 68], sBlo[64 * 68];   // [n][k/2], pitch 68 (==4 mod 32)
    __shared__ U32 sAhi[128 * 12], sAlo[128 * 12]; // [row][k/2 within chunk], pitch 12
    int t = threadIdx.x;
    int warp = t >> 5, lane = t & 31;
    int wm = warp >> 2, wn = warp & 3;
    int rr = lane >> 2, cw = lane & 3;
    int row0 = blockIdx.x << 7;

    // W1 split into smem (once)
    for (int w = t; w < 64 * 64; w += 512) {
        int n = w >> 6, kw = w & 63;
        float v0 = W[(2 * kw) * H1D + n];
        float v1 = W[(2 * kw + 1) * H1D + n];
        U32 whi, wlo;
        split2(v0, v1, whi, wlo);
        sBhi[n * 68 + kw] = whi;
        sBlo[n * 68 + kw] = wlo;
    }

    float acc[2][2][4];
#pragma unroll
    for (int a = 0; a < 2; a++)
#pragma unroll
        for (int b = 0; b < 2; b++)
#pragma unroll
            for (int c = 0; c < 4; c++) acc[a][b][c] = 0.f;

#pragma unroll 1
    for (int kc = 0; kc < 8; kc++) {
#pragma unroll
        for (int i = 0; i < 2; i++) {
            int w = t + (i << 9);
            int r = w >> 3, kw = w & 7;
            float2 v = *(const float2*)&x[(row0 + r) * F_IN + kc * 16 + kw * 2];
            U32 whi, wlo;
            split2(v.x, v.y, whi, wlo);
            sAhi[r * 12 + kw] = whi;
            sAlo[r * 12 + kw] = wlo;
        }
        __syncthreads();
        U32 ahi[2][4], alo[2][4];
#pragma unroll
        for (int mf = 0; mf < 2; mf++) {
            int r0i = wm * 32 + mf * 16 + rr, r8 = r0i + 8;
            ahi[mf][0] = sAhi[r0i * 12 + cw];     ahi[mf][1] = sAhi[r8 * 12 + cw];
            ahi[mf][2] = sAhi[r0i * 12 + 4 + cw]; ahi[mf][3] = sAhi[r8 * 12 + 4 + cw];
            alo[mf][0] = sAlo[r0i * 12 + cw];     alo[mf][1] = sAlo[r8 * 12 + cw];
            alo[mf][2] = sAlo[r0i * 12 + 4 + cw]; alo[mf][3] = sAlo[r8 * 12 + 4 + cw];
        }
#pragma unroll
        for (int nf = 0; nf < 2; nf++) {
            int nb = wn * 16 + nf * 8 + rr;
            int kb = kc * 8 + cw;
            U32 bh0 = sBhi[nb * 68 + kb], bh1 = sBhi[nb * 68 + kb + 4];
            U32 bl0 = sBlo[nb * 68 + kb], bl1 = sBlo[nb * 68 + kb + 4];
#pragma unroll
            for (int mf = 0; mf < 2; mf++) {
                mma16816(acc[mf][nf], ahi[mf], bh0, bh1);
                mma16816(acc[mf][nf], ahi[mf], bl0, bl1);
                mma16816(acc[mf][nf], alo[mf], bh0, bh1);
            }
        }
        __syncthreads();
    }
#pragma unroll
    for (int mf = 0; mf < 2; mf++)
#pragma unroll
        for (int nf = 0; nf < 2; nf++) {
            int r = row0 + wm * 32 + mf * 16 + rr;
            int col = wn * 16 + nf * 8 + cw * 2;
            *(float2*)&g_h1[r * H1D + col]       = make_float2(acc[mf][nf][0], acc[mf][nf][1]);
            *(float2*)&g_h1[(r + 8) * H1D + col] = make_float2(acc[mf][nf][2], acc[mf][nf][3]);
        }
}

// ---------------- aggregation 1 (+bias +ReLU), warp per node, float2 ---------
__global__ void __launch_bounds__(256) agg1_kernel(const float* __restrict__ b1) {
    int node = (blockIdx.x * 256 + threadIdx.x) >> 5;
    int lane = threadIdx.x & 31;
    float di = g_dis[node];
    float d2 = di * di;
    float2 h = ((const float2*)(g_h1 + node * H1D))[lane];
    float ax = d2 * h.x, ay = d2 * h.y;
    int st = g_rowptr[node], c = g_cnt[node];
    int e = 0;
    for (; e + 1 < c; e += 2) {
        float2 e0 = g_csre[st + e], e1 = g_csre[st + e + 1];
        int s0 = __float_as_int(e0.x), s1 = __float_as_int(e1.x);
        float2 p0 = ((const float2*)(g_h1 + s0 * H1D))[lane];
        float2 p1 = ((const float2*)(g_h1 + s1 * H1D))[lane];
        ax += e0.y * p0.x + e1.y * p1.x;
        ay += e0.y * p0.y + e1.y * p1.y;
    }
    if (e < c) {
        float2 e0 = g_csre[st + e];
        int s0 = __float_as_int(e0.x);
        float2 p0 = ((const float2*)(g_h1 + s0 * H1D))[lane];
        ax += e0.y * p0.x;
        ay += e0.y * p0.y;
    }
    float2 bb = ((const float2*)b1)[lane];
    ((float2*)(g_out1 + node * H1D))[lane] =
        make_float2(fmaxf(ax + bb.x, 0.f), fmaxf(ay + bb.y, 0.f));
}

// ---------------- GEMM 2: h2[65536,128] = out1 @ W2[64,128], bf16-split mma --
// 512 thr, block tile 128x128, warp grid 4x4 (warp tile 32x32), K chunks of 16.
__global__ void __launch_bounds__(512) gemm2_kernel(const float* __restrict__ W) {
    __shared__ U32 sBhi[128 * 36], sBlo[128 * 36]; // [n][k/2], pitch 36 (==4 mod 32)
    __shared__ U32 sAhi[128 * 9], sAlo[128 * 9];   // pitch 9 (mild 2-way, fits smem)
    int t = threadIdx.x;
    int warp = t >> 5, lane = t & 31;
    int wm = warp >> 2, wn = warp & 3;
    int rr = lane >> 2, cw = lane & 3;
    int row0 = blockIdx.x << 7;

    for (int w = t; w < 128 * 32; w += 512) {
        int n = w >> 5, kw = w & 31;
        float v0 = W[(2 * kw) * H2D + n];
        float v1 = W[(2 * kw + 1) * H2D + n];
        U32 whi, wlo;
        split2(v0, v1, whi, wlo);
        sBhi[n * 36 + kw] = whi;
        sBlo[n * 36 + kw] = wlo;
    }

    float acc[2][4][4];
#pragma unroll
    for (int a = 0; a < 2; a++)
#pragma unroll
        for (int b = 0; b < 4; b++)
#pragma unroll
            for (int c = 0; c < 4; c++) acc[a][b][c] = 0.f;

#pragma unroll 1
    for (int kc = 0; kc < 4; kc++) {
#pragma unroll
        for (int i = 0; i < 2; i++) {
            int w = t + (i << 9);
            int r = w >> 3, kw = w & 7;
            float2 v = *(const float2*)&g_out1[(row0 + r) * H1D + kc * 16 + kw * 2];
            U32 whi, wlo;
            split2(v.x, v.y, whi, wlo);
            sAhi[r * 9 + kw] = whi;
            sAlo[r * 9 + kw] = wlo;
        }
        __syncthreads();
        U32 ahi[2][4], alo[2][4];
#pragma unroll
        for (int mf = 0; mf < 2; mf++) {
            int r0i = wm * 32 + mf * 16 + rr, r8 = r0i + 8;
            ahi[mf][0] = sAhi[r0i * 9 + cw];     ahi[mf][1] = sAhi[r8 * 9 + cw];
            ahi[mf][2] = sAhi[r0i * 9 + 4 + cw]; ahi[mf][3] = sAhi[r8 * 9 + 4 + cw];
            alo[mf][0] = sAlo[r0i * 9 + cw];     alo[mf][1] = sAlo[r8 * 9 + cw];
            alo[mf][2] = sAlo[r0i * 9 + 4 + cw]; alo[mf][3] = sAlo[r8 * 9 + 4 + cw];
        }
#pragma unroll
        for (int nf = 0; nf < 4; nf++) {
            int nb = wn * 32 + nf * 8 + rr;
            int kb = kc * 8 + cw;
            U32 bh0 = sBhi[nb * 36 + kb], bh1 = sBhi[nb * 36 + kb + 4];
            U32 bl0 = sBlo[nb * 36 + kb], bl1 = sBlo[nb * 36 + kb + 4];
#pragma unroll
            for (int mf = 0; mf < 2; mf++) {
                mma16816(acc[mf][nf], ahi[mf], bh0, bh1);
                mma16816(acc[mf][nf], ahi[mf], bl0, bl1);
                mma16816(acc[mf][nf], alo[mf], bh0, bh1);
            }
        }
        __syncthreads();
    }
#pragma unroll
    for (int mf = 0; mf < 2; mf++)
#pragma unroll
        for (int nf = 0; nf < 4; nf++) {
            int r = row0 + wm * 32 + mf * 16 + rr;
            int col = wn * 32 + nf * 8 + cw * 2;
            *(float2*)&g_h2[r * H2D + col]       = make_float2(acc[mf][nf][0], acc[mf][nf][1]);
            *(float2*)&g_h2[(r + 8) * H2D + col] = make_float2(acc[mf][nf][2], acc[mf][nf][3]);
        }
}

// ---------------- aggregation 2 (+bias +ReLU +pool score), float4 ------------
__global__ void __launch_bounds__(256) agg2_kernel(const float* __restrict__ b2,
                                                   const float* __restrict__ pw) {
    int node = (blockIdx.x * 256 + threadIdx.x) >> 5;
    int lane = threadIdx.x & 31;
    float di = g_dis[node];
    float d2 = di * di;
    float4 h = ((const float4*)(g_h2 + node * H2D))[lane];
    float ax = d2 * h.x, ay = d2 * h.y, az = d2 * h.z, aw = d2 * h.w;
    int st = g_rowptr[node], c = g_cnt[node];
    int e = 0;
    for (; e + 1 < c; e += 2) {
        float2 e0 = g_csre[st + e], e1 = g_csre[st + e + 1];
        int s0 = __float_as_int(e0.x), s1 = __float_as_int(e1.x);
        float4 p0 = ((const float4*)(g_h2 + s0 * H2D))[lane];
        float4 p1 = ((const float4*)(g_h2 + s1 * H2D))[lane];
        ax += e0.y * p0.x + e1.y * p1.x;
        ay += e0.y * p0.y + e1.y * p1.y;
        az += e0.y * p0.z + e1.y * p1.z;
        aw += e0.y * p0.w + e1.y * p1.w;
    }
    if (e < c) {
        float2 e0 = g_csre[st + e];
        int s0 = __float_as_int(e0.x);
        float4 p0 = ((const float4*)(g_h2 + s0 * H2D))[lane];
        ax += e0.y * p0.x;
        ay += e0.y * p0.y;
        az += e0.y * p0.z;
        aw += e0.y * p0.w;
    }
    float4 bb = ((const float4*)b2)[lane];
    float4 o;
    o.x = fmaxf(ax + bb.x, 0.f);
    o.y = fmaxf(ay + bb.y, 0.f);
    o.z = fmaxf(az + bb.z, 0.f);
    o.w = fmaxf(aw + bb.w, 0.f);
    ((float4*)(g_out2 + node * H2D))[lane] = o;
    float4 pv = ((const float4*)pw)[lane];
    float dot = o.x * pv.x + o.y * pv.y + o.z * pv.z + o.w * pv.w;
    float nw  = pv.x * pv.x + pv.y * pv.y + pv.z * pv.z + pv.w * pv.w;
#pragma unroll
    for (int o2 = 16; o2 > 0; o2 >>= 1) {
        dot += __shfl_xor_sync(0xffffffffu, dot, o2);
        nw  += __shfl_xor_sync(0xffffffffu, nw, o2);
    }
    if (lane == 0) g_score[node] = dot * rsqrtf(nw);
}

// ---------------- per-graph: TopK sort, gated max pool, FC, log_softmax -----
__global__ void __launch_bounds__(512) final_kernel(const float* __restrict__ fcW,
                                                    const float* __restrict__ fcb,
                                                    float* __restrict__ out) {
    __shared__ float skey[NPG];
    __shared__ int   sidx[NPG];
    __shared__ float partial[NPG];
    __shared__ float gfeat[H2D];
    __shared__ float logits[NCLS];
    __shared__ float s_lse;
    int b = blockIdx.x, t = threadIdx.x;
    skey[t] = g_score[b * NPG + t];
    sidx[t] = t;
    for (int k = 2; k <= NPG; k <<= 1) {
        for (int j = k >> 1; j > 0; j >>= 1) {
            __syncthreads();
            int ixj = t ^ j;
            if (ixj > t) {
                float ka = skey[t], kb = skey[ixj];
                int ia = sidx[t], ib = sidx[ixj];
                bool bGreater = (kb > ka) || (kb == ka && ib < ia);
                bool desc = ((t & k) == 0);
                if (desc == bGreater) {
                    skey[t] = kb; skey[ixj] = ka;
                    sidx[t] = ib; sidx[ixj] = ia;
                }
            }
        }
    }
    __syncthreads();
    float gate = (t < KSEL) ? tanhf(skey[t]) : 0.f;
    __syncthreads();
    if (t < KSEL) skey[t] = gate;
    __syncthreads();
    {
        int f = t & 127, part = t >> 7;
        float m = -3.4e38f;
        const float* base = g_out2 + (size_t)b * NPG * H2D;
#pragma unroll 4
        for (int kk = part; kk < KSEL; kk += 4) {
            int node = sidx[kk];
            m = fmaxf(m, base[node * H2D + f] * skey[kk]);
        }
        partial[t] = m;
    }
    __syncthreads();
    if (t < H2D)
        gfeat[t] = fmaxf(fmaxf(partial[t], partial[t + 128]),
                         fmaxf(partial[t + 256], partial[t + 384]));
    __syncthreads();
    if (t < NCLS * 32) {
        int c = t >> 5, lane = t & 31;
        float acc = 0.f;
        for (int f = lane; f < H2D; f += 32) acc += gfeat[f] * fcW[f * NCLS + c];
#pragma unroll
        for (int o = 16; o > 0; o >>= 1) acc += __shfl_down_sync(0xffffffffu, acc, o);
        if (lane == 0) logits[c] = acc + fcb[c];
    }
    __syncthreads();
    if (t == 0) {
        float mx = -3.4e38f;
        for (int c = 0; c < NCLS; c++) mx = fmaxf(mx, logits[c]);
        float s = 0.f;
        for (int c = 0; c < NCLS; c++) s += expf(logits[c] - mx);
        s_lse = mx + logf(s);
    }
    __syncthreads();
    if (t < NCLS) out[b * NCLS + t] = logits[t] - s_lse;
}

// ---------------- launch -----------------------------------------------------
extern "C" void kernel_launch(void* const* d_in, const int* in_sizes, int n_in,
                              void* d_out, int out_size) {
    const float* x    = (const float*)d_in[0];
    const int*   ei   = (const int*)d_in[1];
    const float* W1   = (const float*)d_in[3];
    const float* b1   = (const float*)d_in[4];
    const float* W2   = (const float*)d_in[5];
    const float* b2   = (const float*)d_in[6];
    const float* pw   = (const float*)d_in[7];
    const float* fcW  = (const float*)d_in[8];
    const float* fcb  = (const float*)d_in[9];
    float* out = (float*)d_out;

    zero_kernel<<<NNODES / 256, 256>>>();
    detect_kernel<<<1, 256>>>(ei);
    count_kernel<<<NEDGES / 256, 256>>>(ei);
    scan_kernel<<<NGRAPH, NPG>>>();
    scatter_kernel<<<NEDGES / 256, 256>>>(ei);

    gemm1_kernel<<<NNODES / 128, 512>>>(x, W1);
    agg1_kernel<<<NNODES / 8, 256>>>(b1);
    gemm2_kernel<<<NNODES / 128, 512>>>(W2);
    agg2_kernel<<<NNODES / 8, 256>>>(b2, pw);
    final_kernel<<<NGRAPH, NPG>>>(fcW, fcb, out);
}

// round 9
// speedup vs baseline: 1.1068x; 1.1068x over previous
#include <cuda_runtime.h>
#include <cuda_bf16.h>

#define NNODES 65536
#define NEDGES 524288
#define NGRAPH 128
#define NPG    512
#define EPG    4096
#define F_IN   128
#define H1D    64
#define H2D    128
#define NCLS   10
#define KSEL   410

typedef unsigned int U32;

// ---------------- scratch (static device globals; no allocation) -------------
__device__ __align__(16) int    g_cnt[NNODES];
__device__ __align__(16) int    g_rowptr[NNODES];
__device__ __align__(16) float  g_dis[NNODES];
__device__ __align__(16) float2 g_csre[NEDGES];   // (bitcast src idx, edge weight)
__device__ __align__(16) float  g_h1[NNODES * H1D];
__device__ __align__(16) float  g_out1[NNODES * H1D];
__device__ __align__(16) float  g_a2[NNODES * H1D];     // Agg(out1), pre-GEMM2
__device__ __align__(16) float  g_out2[NNODES * H2D];

// ---------------- helpers ----------------------------------------------------
// Split fp32 -> (hi, lo) bf16 pair, packed 2-per-word (even k in low half).
__device__ __forceinline__ void split2(float vx, float vy, U32& whi, U32& wlo) {
    unsigned short h0 = __bfloat16_as_ushort(__float2bfloat16_rn(vx));
    unsigned short h1 = __bfloat16_as_ushort(__float2bfloat16_rn(vy));
    whi = (U32)h0 | ((U32)h1 << 16);
    float r0 = vx - __uint_as_float((U32)h0 << 16);
    float r1 = vy - __uint_as_float((U32)h1 << 16);
    unsigned short l0 = __bfloat16_as_ushort(__float2bfloat16_rn(r0));
    unsigned short l1 = __bfloat16_as_ushort(__float2bfloat16_rn(r1));
    wlo = (U32)l0 | ((U32)l1 << 16);
}

__device__ __forceinline__ void mma16816(float* c, const U32* a, U32 b0, U32 b1) {
    asm volatile(
        "mma.sync.aligned.m16n8k16.row.col.f32.bf16.bf16.f32 "
        "{%0,%1,%2,%3}, {%4,%5,%6,%7}, {%8,%9}, {%0,%1,%2,%3};"
        : "+f"(c[0]), "+f"(c[1]), "+f"(c[2]), "+f"(c[3])
        : "r"(a[0]), "r"(a[1]), "r"(a[2]), "r"(a[3]), "r"(b0), "r"(b1));
}

// ---------------- fused per-graph structure build ----------------------------
// One block per graph: int64/int32 detect, degree count (smem atomics),
// exclusive scan (warp scans), rsqrt degree, and weighted CSR scatter.
__global__ void __launch_bounds__(512) build_kernel(const int* __restrict__ ei) {
    __shared__ int   scnt[NPG];
    __shared__ int   sbase[NPG];
    __shared__ float sdis[NPG];
    __shared__ int   wsum[16];
    __shared__ int   sred;
    int b = blockIdx.x, t = threadIdx.x;
    int lane = t & 31, wid = t >> 5;
    int ebase = b * EPG;

    scnt[t] = 0;
    if (t == 0) sred = 0;
    __syncthreads();

    // local int64 detect: OR the odd 32-bit words of this graph's src slice.
    // Node ids < 2^16, so int64 => all zero. int32 => random src values, OR != 0
    // with overwhelming probability (4096 words).
    int v = 0;
    for (int i = t; i < EPG; i += 512) v |= ei[2 * (ebase + i) + 1];
#pragma unroll
    for (int o = 16; o > 0; o >>= 1) v |= __shfl_xor_sync(0xffffffffu, v, o);
    if (lane == 0 && v) atomicOr(&sred, 1);
    __syncthreads();
    bool is64 = (sred == 0);

    // degree count on smem
    for (int i = t; i < EPG; i += 512) {
        int dv = is64 ? ei[2 * (NEDGES + ebase + i)] : ei[NEDGES + ebase + i];
        atomicAdd(&scnt[dv & (NPG - 1)], 1);
    }
    __syncthreads();
    int c = scnt[t];

    // exclusive scan of degrees (warp scan + cross-warp)
    int inc = c;
#pragma unroll
    for (int o = 1; o < 32; o <<= 1) {
        int u = __shfl_up_sync(0xffffffffu, inc, o);
        if (lane >= o) inc += u;
    }
    if (lane == 31) wsum[wid] = inc;
    __syncthreads();
    if (wid == 0 && lane < 16) {
        int s = wsum[lane];
        int inc2 = s;
#pragma unroll
        for (int o = 1; o < 16; o <<= 1) {
            int u = __shfl_up_sync(0x0000ffffu, inc2, o);
            if (lane >= o) inc2 += u;
        }
        wsum[lane] = inc2 - s;   // exclusive warp prefix
    }
    __syncthreads();
    int rp = ebase + (inc - c) + wsum[wid];

    int node = b * NPG + t;
    g_rowptr[node] = rp;
    g_cnt[node] = c;
    float dis = rsqrtf((float)(c + 1));   // +1 self-loop
    g_dis[node] = dis;
    sbase[t] = rp;
    sdis[t] = dis;
    scnt[t] = 0;                          // reuse as fill counters
    __syncthreads();

    // weighted scatter into CSR
    for (int i = t; i < EPG; i += 512) {
        int sv, dv;
        if (is64) { sv = ei[2 * (ebase + i)]; dv = ei[2 * (NEDGES + ebase + i)]; }
        else      { sv = ei[ebase + i];       dv = ei[NEDGES + ebase + i]; }
        int dl = dv & (NPG - 1);
        int p = atomicAdd(&scnt[dl], 1);
        float w = sdis[sv & (NPG - 1)] * sdis[dl];
        g_csre[sbase[dl] + p] = make_float2(__int_as_float(sv), w);
    }
}

// ---------------- GEMM 1: h1[65536,64] = x @ W1[128,64], bf16-split mma ------
__global__ void __launch_bounds__(512) gemm1_kernel(const float* __restrict__ x,
                                                    const float* __restrict__ W) {
    __shared__ U32 sBhi[64 * 68], sBlo[64 * 68];
    __shared__ U32 sAhi[128 * 12], sAlo[128 * 12];
    int t = threadIdx.x;
    int warp = t >> 5, lane = t & 31;
    int wm = warp >> 2, wn = warp & 3;
    int rr = lane >> 2, cw = lane & 3;
    int row0 = blockIdx.x << 7;

    for (int w = t; w < 64 * 64; w += 512) {
        int n = w >> 6, kw = w & 63;
        float v0 = W[(2 * kw) * H1D + n];
        float v1 = W[(2 * kw + 1) * H1D + n];
        U32 whi, wlo;
        split2(v0, v1, whi, wlo);
        sBhi[n * 68 + kw] = whi;
        sBlo[n * 68 + kw] = wlo;
    }

    float acc[2][2][4];
#pragma unroll
    for (int a = 0; a < 2; a++)
#pragma unroll
        for (int b = 0; b < 2; b++)
#pragma unroll
            for (int c = 0; c < 4; c++) acc[a][b][c] = 0.f;

#pragma unroll 1
    for (int kc = 0; kc < 8; kc++) {
#pragma unroll
        for (int i = 0; i < 2; i++) {
            int w = t + (i << 9);
            int r = w >> 3, kw = w & 7;
            float2 v = *(const float2*)&x[(row0 + r) * F_IN + kc * 16 + kw * 2];
            U32 whi, wlo;
            split2(v.x, v.y, whi, wlo);
            sAhi[r * 12 + kw] = whi;
            sAlo[r * 12 + kw] = wlo;
        }
        __syncthreads();
        U32 ahi[2][4], alo[2][4];
#pragma unroll
        for (int mf = 0; mf < 2; mf++) {
            int r0i = wm * 32 + mf * 16 + rr, r8 = r0i + 8;
            ahi[mf][0] = sAhi[r0i * 12 + cw];     ahi[mf][1] = sAhi[r8 * 12 + cw];
            ahi[mf][2] = sAhi[r0i * 12 + 4 + cw]; ahi[mf][3] = sAhi[r8 * 12 + 4 + cw];
            alo[mf][0] = sAlo[r0i * 12 + cw];     alo[mf][1] = sAlo[r8 * 12 + cw];
            alo[mf][2] = sAlo[r0i * 12 + 4 + cw]; alo[mf][3] = sAlo[r8 * 12 + 4 + cw];
        }
#pragma unroll
        for (int nf = 0; nf < 2; nf++) {
            int nb = wn * 16 + nf * 8 + rr;
            int kb = kc * 8 + cw;
            U32 bh0 = sBhi[nb * 68 + kb], bh1 = sBhi[nb * 68 + kb + 4];
            U32 bl0 = sBlo[nb * 68 + kb], bl1 = sBlo[nb * 68 + kb + 4];
#pragma unroll
            for (int mf = 0; mf < 2; mf++) {
                mma16816(acc[mf][nf], ahi[mf], bh0, bh1);
                mma16816(acc[mf][nf], ahi[mf], bl0, bl1);
                mma16816(acc[mf][nf], alo[mf], bh0, bh1);
            }
        }
        __syncthreads();
    }
#pragma unroll
    for (int mf = 0; mf < 2; mf++)
#pragma unroll
        for (int nf = 0; nf < 2; nf++) {
            int r = row0 + wm * 32 + mf * 16 + rr;
            int col = wn * 16 + nf * 8 + cw * 2;
            *(float2*)&g_h1[r * H1D + col]       = make_float2(acc[mf][nf][0], acc[mf][nf][1]);
            *(float2*)&g_h1[(r + 8) * H1D + col] = make_float2(acc[mf][nf][2], acc[mf][nf][3]);
        }
}

// ---------------- aggregation 1 (+bias +ReLU), warp per node -----------------
__global__ void __launch_bounds__(256) agg1_kernel(const float* __restrict__ b1) {
    int node = (blockIdx.x * 256 + threadIdx.x) >> 5;
    int lane = threadIdx.x & 31;
    float di = g_dis[node];
    float d2 = di * di;
    float2 h = ((const float2*)(g_h1 + node * H1D))[lane];
    float ax = d2 * h.x, ay = d2 * h.y;
    int st = g_rowptr[node], c = g_cnt[node];
    int e = 0;
    for (; e + 1 < c; e += 2) {
        float2 e0 = g_csre[st + e], e1 = g_csre[st + e + 1];
        int s0 = __float_as_int(e0.x), s1 = __float_as_int(e1.x);
        float2 p0 = ((const float2*)(g_h1 + s0 * H1D))[lane];
        float2 p1 = ((const float2*)(g_h1 + s1 * H1D))[lane];
        ax += e0.y * p0.x + e1.y * p1.x;
        ay += e0.y * p0.y + e1.y * p1.y;
    }
    if (e < c) {
        float2 e0 = g_csre[st + e];
        int s0 = __float_as_int(e0.x);
        float2 p0 = ((const float2*)(g_h1 + s0 * H1D))[lane];
        ax += e0.y * p0.x;
        ay += e0.y * p0.y;
    }
    float2 bb = ((const float2*)b1)[lane];
    ((float2*)(g_out1 + node * H1D))[lane] =
        make_float2(fmaxf(ax + bb.x, 0.f), fmaxf(ay + bb.y, 0.f));
}

// ---------------- aggregation 2 PRE-GEMM (linearity: Agg(xW)= (Agg x)W) ------
__global__ void __launch_bounds__(256) agg2pre_kernel() {
    int node = (blockIdx.x * 256 + threadIdx.x) >> 5;
    int lane = threadIdx.x & 31;
    float di = g_dis[node];
    float d2 = di * di;
    float2 h = ((const float2*)(g_out1 + node * H1D))[lane];
    float ax = d2 * h.x, ay = d2 * h.y;
    int st = g_rowptr[node], c = g_cnt[node];
    int e = 0;
    for (; e + 1 < c; e += 2) {
        float2 e0 = g_csre[st + e], e1 = g_csre[st + e + 1];
        int s0 = __float_as_int(e0.x), s1 = __float_as_int(e1.x);
        float2 p0 = ((const float2*)(g_out1 + s0 * H1D))[lane];
        float2 p1 = ((const float2*)(g_out1 + s1 * H1D))[lane];
        ax += e0.y * p0.x + e1.y * p1.x;
        ay += e0.y * p0.y + e1.y * p1.y;
    }
    if (e < c) {
        float2 e0 = g_csre[st + e];
        int s0 = __float_as_int(e0.x);
        float2 p0 = ((const float2*)(g_out1 + s0 * H1D))[lane];
        ax += e0.y * p0.x;
        ay += e0.y * p0.y;
    }
    ((float2*)(g_a2 + node * H1D))[lane] = make_float2(ax, ay);
}

// ---------------- GEMM 2: out2 = relu(a2 @ W2 + b2), bf16-split mma ----------
__global__ void __launch_bounds__(512) gemm2_kernel(const float* __restrict__ W,
                                                    const float* __restrict__ b2) {
    __shared__ U32 sBhi[128 * 36], sBlo[128 * 36];
    __shared__ U32 sAhi[128 * 9], sAlo[128 * 9];
    int t = threadIdx.x;
    int warp = t >> 5, lane = t & 31;
    int wm = warp >> 2, wn = warp & 3;
    int rr = lane >> 2, cw = lane & 3;
    int row0 = blockIdx.x << 7;

    for (int w = t; w < 128 * 32; w += 512) {
        int n = w >> 5, kw = w & 31;
        float v0 = W[(2 * kw) * H2D + n];
        float v1 = W[(2 * kw + 1) * H2D + n];
        U32 whi, wlo;
        split2(v0, v1, whi, wlo);
        sBhi[n * 36 + kw] = whi;
        sBlo[n * 36 + kw] = wlo;
    }

    float acc[2][4][4];
#pragma unroll
    for (int a = 0; a < 2; a++)
#pragma unroll
        for (int b = 0; b < 4; b++)
#pragma unroll
            for (int c = 0; c < 4; c++) acc[a][b][c] = 0.f;

#pragma unroll 1
    for (int kc = 0; kc < 4; kc++) {
#pragma unroll
        for (int i = 0; i < 2; i++) {
            int w = t + (i << 9);
            int r = w >> 3, kw = w & 7;
            float2 v = *(const float2*)&g_a2[(row0 + r) * H1D + kc * 16 + kw * 2];
            U32 whi, wlo;
            split2(v.x, v.y, whi, wlo);
            sAhi[r * 9 + kw] = whi;
            sAlo[r * 9 + kw] = wlo;
        }
        __syncthreads();
        U32 ahi[2][4], alo[2][4];
#pragma unroll
        for (int mf = 0; mf < 2; mf++) {
            int r0i = wm * 32 + mf * 16 + rr, r8 = r0i + 8;
            ahi[mf][0] = sAhi[r0i * 9 + cw];     ahi[mf][1] = sAhi[r8 * 9 + cw];
            ahi[mf][2] = sAhi[r0i * 9 + 4 + cw]; ahi[mf][3] = sAhi[r8 * 9 + 4 + cw];
            alo[mf][0] = sAlo[r0i * 9 + cw];     alo[mf][1] = sAlo[r8 * 9 + cw];
            alo[mf][2] = sAlo[r0i * 9 + 4 + cw]; alo[mf][3] = sAlo[r8 * 9 + 4 + cw];
        }
#pragma unroll
        for (int nf = 0; nf < 4; nf++) {
            int nb = wn * 32 + nf * 8 + rr;
            int kb = kc * 8 + cw;
            U32 bh0 = sBhi[nb * 36 + kb], bh1 = sBhi[nb * 36 + kb + 4];
            U32 bl0 = sBlo[nb * 36 + kb], bl1 = sBlo[nb * 36 + kb + 4];
#pragma unroll
            for (int mf = 0; mf < 2; mf++) {
                mma16816(acc[mf][nf], ahi[mf], bh0, bh1);
                mma16816(acc[mf][nf], ahi[mf], bl0, bl1);
                mma16816(acc[mf][nf], alo[mf], bh0, bh1);
            }
        }
        __syncthreads();
    }
#pragma unroll
    for (int mf = 0; mf < 2; mf++)
#pragma unroll
        for (int nf = 0; nf < 4; nf++) {
            int r = row0 + wm * 32 + mf * 16 + rr;
            int col = wn * 32 + nf * 8 + cw * 2;
            float bb0 = __ldg(&b2[col]), bb1 = __ldg(&b2[col + 1]);
            *(float2*)&g_out2[r * H2D + col] =
                make_float2(fmaxf(acc[mf][nf][0] + bb0, 0.f), fmaxf(acc[mf][nf][1] + bb1, 0.f));
            *(float2*)&g_out2[(r + 8) * H2D + col] =
                make_float2(fmaxf(acc[mf][nf][2] + bb0, 0.f), fmaxf(acc[mf][nf][3] + bb1, 0.f));
        }
}

// ---------------- per-graph: score, TopK sort, gated max pool, FC, softmax ---
__global__ void __launch_bounds__(512) final_kernel(const float* __restrict__ pw,
                                                    const float* __restrict__ fcW,
                                                    const float* __restrict__ fcb,
                                                    float* __restrict__ out) {
    __shared__ float skey[NPG];
    __shared__ int   sidx[NPG];
    __shared__ float partial[NPG];
    __shared__ float gfeat[H2D];
    __shared__ float logits[NCLS];
    __shared__ float s_lse;
    int b = blockIdx.x, t = threadIdx.x;
    int warp = t >> 5, lane = t & 31;
    const float* base = g_out2 + (size_t)b * NPG * H2D;

    // score pre-pass: warp per 32 nodes, row dot with pool_w (coalesced float4)
    {
        float4 pv = ((const float4*)pw)[lane];
        float nw = pv.x * pv.x + pv.y * pv.y + pv.z * pv.z + pv.w * pv.w;
#pragma unroll
        for (int o = 16; o > 0; o >>= 1) nw += __shfl_xor_sync(0xffffffffu, nw, o);
        float rnorm = rsqrtf(nw);
        for (int n = warp; n < NPG; n += 16) {
            float4 h = ((const float4*)(base + n * H2D))[lane];
            float d = h.x * pv.x + h.y * pv.y + h.z * pv.z + h.w * pv.w;
#pragma unroll
            for (int o = 16; o > 0; o >>= 1) d += __shfl_xor_sync(0xffffffffu, d, o);
            if (lane == 0) { skey[n] = d * rnorm; sidx[n] = n; }
        }
    }
    // bitonic sort, descending, tie-break: smaller index ranks higher
    for (int k = 2; k <= NPG; k <<= 1) {
        for (int j = k >> 1; j > 0; j >>= 1) {
            __syncthreads();
            int ixj = t ^ j;
            if (ixj > t) {
                float ka = skey[t], kb = skey[ixj];
                int ia = sidx[t], ib = sidx[ixj];
                bool bGreater = (kb > ka) || (kb == ka && ib < ia);
                bool desc = ((t & k) == 0);
                if (desc == bGreater) {
                    skey[t] = kb; skey[ixj] = ka;
                    sidx[t] = ib; sidx[ixj] = ia;
                }
            }
        }
    }
    __syncthreads();
    float gate = (t < KSEL) ? tanhf(skey[t]) : 0.f;
    __syncthreads();
    if (t < KSEL) skey[t] = gate;
    __syncthreads();
    // gated max over selected nodes: 4 partitions x 128 features
    {
        int f = t & 127, part = t >> 7;
        float m = -3.4e38f;
#pragma unroll 4
        for (int kk = part; kk < KSEL; kk += 4) {
            int node = sidx[kk];
            m = fmaxf(m, base[node * H2D + f] * skey[kk]);
        }
        partial[t] = m;
    }
    __syncthreads();
    if (t < H2D)
        gfeat[t] = fmaxf(fmaxf(partial[t], partial[t + 128]),
                         fmaxf(partial[t + 256], partial[t + 384]));
    __syncthreads();
    if (t < NCLS * 32) {
        int c = t >> 5, ln = t & 31;
        float acc = 0.f;
        for (int f = ln; f < H2D; f += 32) acc += gfeat[f] * fcW[f * NCLS + c];
#pragma unroll
        for (int o = 16; o > 0; o >>= 1) acc += __shfl_down_sync(0xffffffffu, acc, o);
        if (ln == 0) logits[c] = acc + fcb[c];
    }
    __syncthreads();
    if (t == 0) {
        float mx = -3.4e38f;
        for (int c = 0; c < NCLS; c++) mx = fmaxf(mx, logits[c]);
        float s = 0.f;
        for (int c = 0; c < NCLS; c++) s += expf(logits[c] - mx);
        s_lse = mx + logf(s);
    }
    __syncthreads();
    if (t < NCLS) out[b * NCLS + t] = logits[t] - s_lse;
}

// ---------------- launch -----------------------------------------------------
extern "C" void kernel_launch(void* const* d_in, const int* in_sizes, int n_in,
                              void* d_out, int out_size) {
    const float* x    = (const float*)d_in[0];
    const int*   ei   = (const int*)d_in[1];
    const float* W1   = (const float*)d_in[3];
    const float* b1   = (const float*)d_in[4];
    const float* W2   = (const float*)d_in[5];
    const float* b2   = (const float*)d_in[6];
    const float* pw   = (const float*)d_in[7];
    const float* fcW  = (const float*)d_in[8];
    const float* fcb  = (const float*)d_in[9];
    float* out = (float*)d_out;

    build_kernel<<<NGRAPH, 512>>>(ei);
    gemm1_kernel<<<NNODES / 128, 512>>>(x, W1);
    agg1_kernel<<<NNODES / 8, 256>>>(b1);
    agg2pre_kernel<<<NNODES / 8, 256>>>();
    gemm2_kernel<<<NNODES / 128, 512>>>(W2, b2);
    final_kernel<<<NGRAPH, 512>>>(pw, fcW, fcb, out);
}

// round 12
// speedup vs baseline: 1.2709x; 1.1483x over previous
#include <cuda_runtime.h>
#include <cuda_bf16.h>

#define NNODES 65536
#define NEDGES 524288
#define NGRAPH 128
#define NPG    512
#define EPG    4096
#define F_IN   128
#define H1D    64
#define H2D    128
#define NCLS   10
#define KSEL   410

typedef unsigned int U32;

// ---------------- scratch (static device globals; no allocation) -------------
__device__ __align__(16) int    g_cnt[NNODES];
__device__ __align__(16) int    g_rowptr[NNODES];
__device__ __align__(16) float  g_dis[NNODES];
__device__ __align__(16) float2 g_csre[NEDGES];   // (bitcast src idx, edge weight)
__device__ __align__(16) float  g_h1[NNODES * H1D];
__device__ __align__(16) float  g_out1[NNODES * H1D];   // staging between agg phases
__device__ __align__(16) float  g_a2[NNODES * H1D];     // Agg(out1), pre-GEMM2
__device__ __align__(16) float  g_out2[NNODES * H2D];

// ---------------- helpers ----------------------------------------------------
__device__ __forceinline__ void split2(float vx, float vy, U32& whi, U32& wlo) {
    unsigned short h0 = __bfloat16_as_ushort(__float2bfloat16_rn(vx));
    unsigned short h1 = __bfloat16_as_ushort(__float2bfloat16_rn(vy));
    whi = (U32)h0 | ((U32)h1 << 16);
    float r0 = vx - __uint_as_float((U32)h0 << 16);
    float r1 = vy - __uint_as_float((U32)h1 << 16);
    unsigned short l0 = __bfloat16_as_ushort(__float2bfloat16_rn(r0));
    unsigned short l1 = __bfloat16_as_ushort(__float2bfloat16_rn(r1));
    wlo = (U32)l0 | ((U32)l1 << 16);
}

__device__ __forceinline__ void mma16816(float* c, const U32* a, U32 b0, U32 b1) {
    asm volatile(
        "mma.sync.aligned.m16n8k16.row.col.f32.bf16.bf16.f32 "
        "{%0,%1,%2,%3}, {%4,%5,%6,%7}, {%8,%9}, {%0,%1,%2,%3};"
        : "+f"(c[0]), "+f"(c[1]), "+f"(c[2]), "+f"(c[3])
        : "r"(a[0]), "r"(a[1]), "r"(a[2]), "r"(a[3]), "r"(b0), "r"(b1));
}

// ---------------- fused per-graph structure build ----------------------------
__global__ void __launch_bounds__(512) build_kernel(const int* __restrict__ ei) {
    __shared__ int   scnt[NPG];
    __shared__ int   sbase[NPG];
    __shared__ float sdis[NPG];
    __shared__ int   wsum[16];
    __shared__ int   sred;
    int b = blockIdx.x, t = threadIdx.x;
    int lane = t & 31, wid = t >> 5;
    int ebase = b * EPG;

    scnt[t] = 0;
    if (t == 0) sred = 0;
    __syncthreads();

    // int64 detect on this graph's src slice (node ids < 2^16)
    int v = 0;
    for (int i = t; i < EPG; i += 512) v |= ei[2 * (ebase + i) + 1];
#pragma unroll
    for (int o = 16; o > 0; o >>= 1) v |= __shfl_xor_sync(0xffffffffu, v, o);
    if (lane == 0 && v) atomicOr(&sred, 1);
    __syncthreads();
    bool is64 = (sred == 0);

    for (int i = t; i < EPG; i += 512) {
        int dv = is64 ? ei[2 * (NEDGES + ebase + i)] : ei[NEDGES + ebase + i];
        atomicAdd(&scnt[dv & (NPG - 1)], 1);
    }
    __syncthreads();
    int c = scnt[t];

    int inc = c;
#pragma unroll
    for (int o = 1; o < 32; o <<= 1) {
        int u = __shfl_up_sync(0xffffffffu, inc, o);
        if (lane >= o) inc += u;
    }
    if (lane == 31) wsum[wid] = inc;
    __syncthreads();
    if (wid == 0 && lane < 16) {
        int s = wsum[lane];
        int inc2 = s;
#pragma unroll
        for (int o = 1; o < 16; o <<= 1) {
            int u = __shfl_up_sync(0x0000ffffu, inc2, o);
            if (lane >= o) inc2 += u;
        }
        wsum[lane] = inc2 - s;
    }
    __syncthreads();
    int rp = ebase + (inc - c) + wsum[wid];

    int node = b * NPG + t;
    g_rowptr[node] = rp;
    g_cnt[node] = c;
    float dis = rsqrtf((float)(c + 1));
    g_dis[node] = dis;
    sbase[t] = rp;
    sdis[t] = dis;
    scnt[t] = 0;
    __syncthreads();

    for (int i = t; i < EPG; i += 512) {
        int sv, dv;
        if (is64) { sv = ei[2 * (ebase + i)]; dv = ei[2 * (NEDGES + ebase + i)]; }
        else      { sv = ei[ebase + i];       dv = ei[NEDGES + ebase + i]; }
        int dl = dv & (NPG - 1);
        int p = atomicAdd(&scnt[dl], 1);
        float w = sdis[sv & (NPG - 1)] * sdis[dl];
        g_csre[sbase[dl] + p] = make_float2(__int_as_float(sv), w);
    }
}

// ---------------- GEMM 1: h1[65536,64] = x @ W1[128,64], bf16-split mma ------
__global__ void __launch_bounds__(512) gemm1_kernel(const float* __restrict__ x,
                                                    const float* __restrict__ W) {
    __shared__ U32 sBhi[64 * 68], sBlo[64 * 68];
    __shared__ U32 sAhi[128 * 12], sAlo[128 * 12];
    int t = threadIdx.x;
    int warp = t >> 5, lane = t & 31;
    int wm = warp >> 2, wn = warp & 3;
    int rr = lane >> 2, cw = lane & 3;
    int row0 = blockIdx.x << 7;

    for (int w = t; w < 64 * 64; w += 512) {
        int n = w >> 6, kw = w & 63;
        float v0 = W[(2 * kw) * H1D + n];
        float v1 = W[(2 * kw + 1) * H1D + n];
        U32 whi, wlo;
        split2(v0, v1, whi, wlo);
        sBhi[n * 68 + kw] = whi;
        sBlo[n * 68 + kw] = wlo;
    }

    float acc[2][2][4];
#pragma unroll
    for (int a = 0; a < 2; a++)
#pragma unroll
        for (int b = 0; b < 2; b++)
#pragma unroll
            for (int c = 0; c < 4; c++) acc[a][b][c] = 0.f;

#pragma unroll 1
    for (int kc = 0; kc < 8; kc++) {
#pragma unroll
        for (int i = 0; i < 2; i++) {
            int w = t + (i << 9);
            int r = w >> 3, kw = w & 7;
            float2 v = *(const float2*)&x[(row0 + r) * F_IN + kc * 16 + kw * 2];
            U32 whi, wlo;
            split2(v.x, v.y, whi, wlo);
            sAhi[r * 12 + kw] = whi;
            sAlo[r * 12 + kw] = wlo;
        }
        __syncthreads();
        U32 ahi[2][4], alo[2][4];
#pragma unroll
        for (int mf = 0; mf < 2; mf++) {
            int r0i = wm * 32 + mf * 16 + rr, r8 = r0i + 8;
            ahi[mf][0] = sAhi[r0i * 12 + cw];     ahi[mf][1] = sAhi[r8 * 12 + cw];
            ahi[mf][2] = sAhi[r0i * 12 + 4 + cw]; ahi[mf][3] = sAhi[r8 * 12 + 4 + cw];
            alo[mf][0] = sAlo[r0i * 12 + cw];     alo[mf][1] = sAlo[r8 * 12 + cw];
            alo[mf][2] = sAlo[r0i * 12 + 4 + cw]; alo[mf][3] = sAlo[r8 * 12 + 4 + cw];
        }
#pragma unroll
        for (int nf = 0; nf < 2; nf++) {
            int nb = wn * 16 + nf * 8 + rr;
            int kb = kc * 8 + cw;
            U32 bh0 = sBhi[nb * 68 + kb], bh1 = sBhi[nb * 68 + kb + 4];
            U32 bl0 = sBlo[nb * 68 + kb], bl1 = sBlo[nb * 68 + kb + 4];
#pragma unroll
            for (int mf = 0; mf < 2; mf++) {
                mma16816(acc[mf][nf], ahi[mf], bh0, bh1);
                mma16816(acc[mf][nf], ahi[mf], bl0, bl1);
                mma16816(acc[mf][nf], alo[mf], bh0, bh1);
            }
        }
        __syncthreads();
    }
#pragma unroll
    for (int mf = 0; mf < 2; mf++)
#pragma unroll
        for (int nf = 0; nf < 2; nf++) {
            int r = row0 + wm * 32 + mf * 16 + rr;
            int col = wn * 16 + nf * 8 + cw * 2;
            *(float2*)&g_h1[r * H1D + col]       = make_float2(acc[mf][nf][0], acc[mf][nf][1]);
            *(float2*)&g_h1[(r + 8) * H1D + col] = make_float2(acc[mf][nf][2], acc[mf][nf][3]);
        }
}

// ---------------- fused aggregation (both GCN hops), block per graph ---------
// smem: feature slice 128 KB + edge list 32 KB + cnt/rowptr 4 KB = 164 KB.
// Phase 1: out1 = relu(Agg(h1)+b1) from smem, staged to global.
// Phase 2: reload out1 slice, a2 = Agg(out1). Random reads all hit LDS.
#define AGG_SMEM (131072 + 32768 + 2048 + 2048)
__global__ void __launch_bounds__(1024) aggf_kernel(const float* __restrict__ b1) {
    extern __shared__ char sm[];
    float2* sfeat = (float2*)sm;                              // 512 * 32 float2
    float2* sedge = (float2*)(sm + 131072);                   // 4096
    int*    scnt  = (int*)(sm + 131072 + 32768);              // 512
    int*    srp   = (int*)(sm + 131072 + 32768 + 2048);       // 512
    int b = blockIdx.x, t = threadIdx.x;
    int lane = t & 31, wid = t >> 5;
    int nbase = b * NPG;
    int ebase = b * EPG;

    float4* dst4 = (float4*)sfeat;
    {
        const float4* src = (const float4*)(g_h1 + (size_t)nbase * H1D);
#pragma unroll
        for (int i = 0; i < 8; i++) dst4[t + i * 1024] = src[t + i * 1024];
        const float4* esrc = (const float4*)(g_csre + ebase);
        float4* edst = (float4*)sedge;
#pragma unroll
        for (int i = 0; i < 2; i++) edst[t + i * 1024] = esrc[t + i * 1024];
        if (t < NPG) {
            scnt[t] = g_cnt[nbase + t];
            srp[t]  = g_rowptr[nbase + t] - ebase;
        }
    }
    __syncthreads();

    float2 bb = ((const float2*)b1)[lane];

    // phase 1: out1 = relu(Agg(h1) + b1)
    for (int n = wid; n < NPG; n += 32) {
        int c = scnt[n], st = srp[n];
        float di = rsqrtf((float)(c + 1));
        float d2 = di * di;
        float2 h = sfeat[n * 32 + lane];
        float ax = d2 * h.x, ay = d2 * h.y;
        int e = 0;
        for (; e + 1 < c; e += 2) {
            float2 e0 = sedge[st + e], e1 = sedge[st + e + 1];
            int s0 = __float_as_int(e0.x) & (NPG - 1);
            int s1 = __float_as_int(e1.x) & (NPG - 1);
            float2 p0 = sfeat[s0 * 32 + lane];
            float2 p1 = sfeat[s1 * 32 + lane];
            ax += e0.y * p0.x + e1.y * p1.x;
            ay += e0.y * p0.y + e1.y * p1.y;
        }
        if (e < c) {
            float2 e0 = sedge[st + e];
            int s0 = __float_as_int(e0.x) & (NPG - 1);
            float2 p0 = sfeat[s0 * 32 + lane];
            ax += e0.y * p0.x;
            ay += e0.y * p0.y;
        }
        ((float2*)g_out1)[(nbase + n) * 32 + lane] =
            make_float2(fmaxf(ax + bb.x, 0.f), fmaxf(ay + bb.y, 0.f));
    }
    __syncthreads();   // out1 writes visible block-wide; smem reuse safe

    // reload out1 slice into the same smem buffer
    {
        const float4* src = (const float4*)(g_out1 + (size_t)nbase * H1D);
#pragma unroll
        for (int i = 0; i < 8; i++) dst4[t + i * 1024] = src[t + i * 1024];
    }
    __syncthreads();

    // phase 2: a2 = Agg(out1)
    for (int n = wid; n < NPG; n += 32) {
        int c = scnt[n], st = srp[n];
        float di = rsqrtf((float)(c + 1));
        float d2 = di * di;
        float2 h = sfeat[n * 32 + lane];
        float ax = d2 * h.x, ay = d2 * h.y;
        int e = 0;
        for (; e + 1 < c; e += 2) {
            float2 e0 = sedge[st + e], e1 = sedge[st + e + 1];
            int s0 = __float_as_int(e0.x) & (NPG - 1);
            int s1 = __float_as_int(e1.x) & (NPG - 1);
            float2 p0 = sfeat[s0 * 32 + lane];
            float2 p1 = sfeat[s1 * 32 + lane];
            ax += e0.y * p0.x + e1.y * p1.x;
            ay += e0.y * p0.y + e1.y * p1.y;
        }
        if (e < c) {
            float2 e0 = sedge[st + e];
            int s0 = __float_as_int(e0.x) & (NPG - 1);
            float2 p0 = sfeat[s0 * 32 + lane];
            ax += e0.y * p0.x;
            ay += e0.y * p0.y;
        }
        ((float2*)g_a2)[(nbase + n) * 32 + lane] = make_float2(ax, ay);
    }
}

// ---------------- GEMM 2: out2 = relu(a2 @ W2 + b2), bf16-split mma ----------
__global__ void __launch_bounds__(512) gemm2_kernel(const float* __restrict__ W,
                                                    const float* __restrict__ b2) {
    __shared__ U32 sBhi[128 * 36], sBlo[128 * 36];
    __shared__ U32 sAhi[128 * 9], sAlo[128 * 9];
    int t = threadIdx.x;
    int warp = t >> 5, lane = t & 31;
    int wm = warp >> 2, wn = warp & 3;
    int rr = lane >> 2, cw = lane & 3;
    int row0 = blockIdx.x << 7;

    for (int w = t; w < 128 * 32; w += 512) {
        int n = w >> 5, kw = w & 31;
        float v0 = W[(2 * kw) * H2D + n];
        float v1 = W[(2 * kw + 1) * H2D + n];
        U32 whi, wlo;
        split2(v0, v1, whi, wlo);
        sBhi[n * 36 + kw] = whi;
        sBlo[n * 36 + kw] = wlo;
    }

    float acc[2][4][4];
#pragma unroll
    for (int a = 0; a < 2; a++)
#pragma unroll
        for (int b = 0; b < 4; b++)
#pragma unroll
            for (int c = 0; c < 4; c++) acc[a][b][c] = 0.f;

#pragma unroll 1
    for (int kc = 0; kc < 4; kc++) {
#pragma unroll
        for (int i = 0; i < 2; i++) {
            int w = t + (i << 9);
            int r = w >> 3, kw = w & 7;
            float2 v = *(const float2*)&g_a2[(row0 + r) * H1D + kc * 16 + kw * 2];
            U32 whi, wlo;
            split2(v.x, v.y, whi, wlo);
            sAhi[r * 9 + kw] = whi;
            sAlo[r * 9 + kw] = wlo;
        }
        __syncthreads();
        U32 ahi[2][4], alo[2][4];
#pragma unroll
        for (int mf = 0; mf < 2; mf++) {
            int r0i = wm * 32 + mf * 16 + rr, r8 = r0i + 8;
            ahi[mf][0] = sAhi[r0i * 9 + cw];     ahi[mf][1] = sAhi[r8 * 9 + cw];
            ahi[mf][2] = sAhi[r0i * 9 + 4 + cw]; ahi[mf][3] = sAhi[r8 * 9 + 4 + cw];
            alo[mf][0] = sAlo[r0i * 9 + cw];     alo[mf][1] = sAlo[r8 * 9 + cw];
            alo[mf][2] = sAlo[r0i * 9 + 4 + cw]; alo[mf][3] = sAlo[r8 * 9 + 4 + cw];
        }
#pragma unroll
        for (int nf = 0; nf < 4; nf++) {
            int nb = wn * 32 + nf * 8 + rr;
            int kb = kc * 8 + cw;
            U32 bh0 = sBhi[nb * 36 + kb], bh1 = sBhi[nb * 36 + kb + 4];
            U32 bl0 = sBlo[nb * 36 + kb], bl1 = sBlo[nb * 36 + kb + 4];
#pragma unroll
            for (int mf = 0; mf < 2; mf++) {
                mma16816(acc[mf][nf], ahi[mf], bh0, bh1);
                mma16816(acc[mf][nf], ahi[mf], bl0, bl1);
                mma16816(acc[mf][nf], alo[mf], bh0, bh1);
            }
        }
        __syncthreads();
    }
#pragma unroll
    for (int mf = 0; mf < 2; mf++)
#pragma unroll
        for (int nf = 0; nf < 4; nf++) {
            int r = row0 + wm * 32 + mf * 16 + rr;
            int col = wn * 32 + nf * 8 + cw * 2;
            float bb0 = __ldg(&b2[col]), bb1 = __ldg(&b2[col + 1]);
            *(float2*)&g_out2[r * H2D + col] =
                make_float2(fmaxf(acc[mf][nf][0] + bb0, 0.f), fmaxf(acc[mf][nf][1] + bb1, 0.f));
            *(float2*)&g_out2[(r + 8) * H2D + col] =
                make_float2(fmaxf(acc[mf][nf][2] + bb0, 0.f), fmaxf(acc[mf][nf][3] + bb1, 0.f));
        }
}

// ---------------- per-graph: score, TopK sort, gated max pool, FC, softmax ---
__global__ void __launch_bounds__(512) final_kernel(const float* __restrict__ pw,
                                                    const float* __restrict__ fcW,
                                                    const float* __restrict__ fcb,
                                                    float* __restrict__ out) {
    __shared__ float skey[NPG];
    __shared__ int   sidx[NPG];
    __shared__ float partial[NPG];
    __shared__ float gfeat[H2D];
    __shared__ float logits[NCLS];
    __shared__ float s_lse;
    int b = blockIdx.x, t = threadIdx.x;
    int warp = t >> 5, lane = t & 31;
    const float* base = g_out2 + (size_t)b * NPG * H2D;

    {
        float4 pv = ((const float4*)pw)[lane];
        float nw = pv.x * pv.x + pv.y * pv.y + pv.z * pv.z + pv.w * pv.w;
#pragma unroll
        for (int o = 16; o > 0; o >>= 1) nw += __shfl_xor_sync(0xffffffffu, nw, o);
        float rnorm = rsqrtf(nw);
        for (int n = warp; n < NPG; n += 16) {
            float4 h = ((const float4*)(base + n * H2D))[lane];
            float d = h.x * pv.x + h.y * pv.y + h.z * pv.z + h.w * pv.w;
#pragma unroll
            for (int o = 16; o > 0; o >>= 1) d += __shfl_xor_sync(0xffffffffu, d, o);
            if (lane == 0) { skey[n] = d * rnorm; sidx[n] = n; }
        }
    }
    for (int k = 2; k <= NPG; k <<= 1) {
        for (int j = k >> 1; j > 0; j >>= 1) {
            __syncthreads();
            int ixj = t ^ j;
            if (ixj > t) {
                float ka = skey[t], kb = skey[ixj];
                int ia = sidx[t], ib = sidx[ixj];
                bool bGreater = (kb > ka) || (kb == ka && ib < ia);
                bool desc = ((t & k) == 0);
                if (desc == bGreater) {
                    skey[t] = kb; skey[ixj] = ka;
                    sidx[t] = ib; sidx[ixj] = ia;
                }
            }
        }
    }
    __syncthreads();
    float gate = (t < KSEL) ? tanhf(skey[t]) : 0.f;
    __syncthreads();
    if (t < KSEL) skey[t] = gate;
    __syncthreads();
    {
        int f = t & 127, part = t >> 7;
        float m = -3.4e38f;
#pragma unroll 4
        for (int kk = part; kk < KSEL; kk += 4) {
            int node = sidx[kk];
            m = fmaxf(m, base[node * H2D + f] * skey[kk]);
        }
        partial[t] = m;
    }
    __syncthreads();
    if (t < H2D)
        gfeat[t] = fmaxf(fmaxf(partial[t], partial[t + 128]),
                         fmaxf(partial[t + 256], partial[t + 384]));
    __syncthreads();
    if (t < NCLS * 32) {
        int c = t >> 5, ln = t & 31;
        float acc = 0.f;
        for (int f = ln; f < H2D; f += 32) acc += gfeat[f] * fcW[f * NCLS + c];
#pragma unroll
        for (int o = 16; o > 0; o >>= 1) acc += __shfl_down_sync(0xffffffffu, acc, o);
        if (ln == 0) logits[c] = acc + fcb[c];
    }
    __syncthreads();
    if (t == 0) {
        float mx = -3.4e38f;
        for (int c = 0; c < NCLS; c++) mx = fmaxf(mx, logits[c]);
        float s = 0.f;
        for (int c = 0; c < NCLS; c++) s += expf(logits[c] - mx);
        s_lse = mx + logf(s);
    }
    __syncthreads();
    if (t < NCLS) out[b * NCLS + t] = logits[t] - s_lse;
}

// ---------------- launch -----------------------------------------------------
extern "C" void kernel_launch(void* const* d_in, const int* in_sizes, int n_in,
                              void* d_out, int out_size) {
    const float* x    = (const float*)d_in[0];
    const int*   ei   = (const int*)d_in[1];
    const float* W1   = (const float*)d_in[3];
    const float* b1   = (const float*)d_in[4];
    const float* W2   = (const float*)d_in[5];
    const float* b2   = (const float*)d_in[6];
    const float* pw   = (const float*)d_in[7];
    const float* fcW  = (const float*)d_in[8];
    const float* fcb  = (const float*)d_in[9];
    float* out = (float*)d_out;

    cudaFuncSetAttribute(aggf_kernel,
                         cudaFuncAttributeMaxDynamicSharedMemorySize, AGG_SMEM);

    build_kernel<<<NGRAPH, 512>>>(ei);
    gemm1_kernel<<<NNODES / 128, 512>>>(x, W1);
    aggf_kernel<<<NGRAPH, 1024, AGG_SMEM>>>(b1);
    gemm2_kernel<<<NNODES / 128, 512>>>(W2, b2);
    final_kernel<<<NGRAPH, 512>>>(pw, fcW, fcb, out);
}

// round 14
// speedup vs baseline: 1.3301x; 1.0466x over previous
#include <cuda_runtime.h>
#include <cuda_bf16.h>

#define NNODES 65536
#define NEDGES 524288
#define NGRAPH 128
#define NPG    512
#define EPG    4096
#define F_IN   128
#define H1D    64
#define H2D    128
#define NCLS   10
#define KSEL   410

typedef unsigned int U32;

// ---------------- scratch (static device globals; no allocation) -------------
__device__ __align__(16) int    g_cnt[NNODES];
__device__ __align__(16) int    g_rowptr[NNODES];
__device__ __align__(16) float  g_dis[NNODES];
__device__ __align__(16) float2 g_csre[NEDGES];   // (bitcast src idx, edge weight)
__device__ __align__(16) float  g_h1[NNODES * H1D];
__device__ __align__(16) float  g_out1[NNODES * H1D];   // staging between agg phases
__device__ __align__(16) float  g_a2[NNODES * H1D];     // Agg(out1), pre-GEMM2
__device__ __align__(16) float  g_out2[NNODES * H2D];

// ---------------- helpers ----------------------------------------------------
__device__ __forceinline__ void split2(float vx, float vy, U32& whi, U32& wlo) {
    unsigned short h0 = __bfloat16_as_ushort(__float2bfloat16_rn(vx));
    unsigned short h1 = __bfloat16_as_ushort(__float2bfloat16_rn(vy));
    whi = (U32)h0 | ((U32)h1 << 16);
    float r0 = vx - __uint_as_float((U32)h0 << 16);
    float r1 = vy - __uint_as_float((U32)h1 << 16);
    unsigned short l0 = __bfloat16_as_ushort(__float2bfloat16_rn(r0));
    unsigned short l1 = __bfloat16_as_ushort(__float2bfloat16_rn(r1));
    wlo = (U32)l0 | ((U32)l1 << 16);
}

__device__ __forceinline__ void mma16816(float* c, const U32* a, U32 b0, U32 b1) {
    asm volatile(
        "mma.sync.aligned.m16n8k16.row.col.f32.bf16.bf16.f32 "
        "{%0,%1,%2,%3}, {%4,%5,%6,%7}, {%8,%9}, {%0,%1,%2,%3};"
        : "+f"(c[0]), "+f"(c[1]), "+f"(c[2]), "+f"(c[3])
        : "r"(a[0]), "r"(a[1]), "r"(a[2]), "r"(a[3]), "r"(b0), "r"(b1));
}

// ---------------- fused per-graph structure build ----------------------------
__global__ void __launch_bounds__(512) build_kernel(const int* __restrict__ ei) {
    __shared__ int   scnt[NPG];
    __shared__ int   sbase[NPG];
    __shared__ float sdis[NPG];
    __shared__ int   wsum[16];
    __shared__ int   sred;
    int b = blockIdx.x, t = threadIdx.x;
    int lane = t & 31, wid = t >> 5;
    int ebase = b * EPG;

    scnt[t] = 0;
    if (t == 0) sred = 0;
    __syncthreads();

    // int64 detect on this graph's src slice (node ids < 2^16)
    int v = 0;
    for (int i = t; i < EPG; i += 512) v |= ei[2 * (ebase + i) + 1];
#pragma unroll
    for (int o = 16; o > 0; o >>= 1) v |= __shfl_xor_sync(0xffffffffu, v, o);
    if (lane == 0 && v) atomicOr(&sred, 1);
    __syncthreads();
    bool is64 = (sred == 0);

    for (int i = t; i < EPG; i += 512) {
        int dv = is64 ? ei[2 * (NEDGES + ebase + i)] : ei[NEDGES + ebase + i];
        atomicAdd(&scnt[dv & (NPG - 1)], 1);
    }
    __syncthreads();
    int c = scnt[t];

    int inc = c;
#pragma unroll
    for (int o = 1; o < 32; o <<= 1) {
        int u = __shfl_up_sync(0xffffffffu, inc, o);
        if (lane >= o) inc += u;
    }
    if (lane == 31) wsum[wid] = inc;
    __syncthreads();
    if (wid == 0 && lane < 16) {
        int s = wsum[lane];
        int inc2 = s;
#pragma unroll
        for (int o = 1; o < 16; o <<= 1) {
            int u = __shfl_up_sync(0x0000ffffu, inc2, o);
            if (lane >= o) inc2 += u;
        }
        wsum[lane] = inc2 - s;
    }
    __syncthreads();
    int rp = ebase + (inc - c) + wsum[wid];

    int node = b * NPG + t;
    g_rowptr[node] = rp;
    g_cnt[node] = c;
    float dis = rsqrtf((float)(c + 1));
    g_dis[node] = dis;
    sbase[t] = rp;
    sdis[t] = dis;
    scnt[t] = 0;
    __syncthreads();

    for (int i = t; i < EPG; i += 512) {
        int sv, dv;
        if (is64) { sv = ei[2 * (ebase + i)]; dv = ei[2 * (NEDGES + ebase + i)]; }
        else      { sv = ei[ebase + i];       dv = ei[NEDGES + ebase + i]; }
        int dl = dv & (NPG - 1);
        int p = atomicAdd(&scnt[dl], 1);
        float w = sdis[sv & (NPG - 1)] * sdis[dl];
        g_csre[sbase[dl] + p] = make_float2(__int_as_float(sv), w);
    }
}

// ---------------- GEMM 1: h1 = x @ W1, single-stage smem, unbroken mma -------
// A: 128 rows x 64 kwords, pitch 68 (bank = 4r+kw mod 32, conflict-free).
// B: 64 n x 64 kwords, pitch 68. One sync, then 8 k-chunks of pure LDS+mma.
__global__ void __launch_bounds__(512) gemm1_kernel(const float* __restrict__ x,
                                                    const float* __restrict__ W) {
    __shared__ U32 sAhi[128 * 68], sAlo[128 * 68];
    __shared__ U32 sBhi[64 * 68],  sBlo[64 * 68];
    int t = threadIdx.x;
    int warp = t >> 5, lane = t & 31;
    int wm = warp >> 2, wn = warp & 3;
    int rr = lane >> 2, cw = lane & 3;
    int row0 = blockIdx.x << 7;

    // stage B (W1): 64 x 64 kwords
#pragma unroll
    for (int i = 0; i < 8; i++) {
        int w = t + (i << 9);
        int n = w >> 6, kw = w & 63;
        float v0 = W[(2 * kw) * H1D + n];
        float v1 = W[(2 * kw + 1) * H1D + n];
        U32 whi, wlo;
        split2(v0, v1, whi, wlo);
        sBhi[n * 68 + kw] = whi;
        sBlo[n * 68 + kw] = wlo;
    }
    // stage A (x): 128 rows x 64 kwords
#pragma unroll
    for (int i = 0; i < 16; i++) {
        int w = t + (i << 9);
        int r = w >> 6, kw = w & 63;
        float2 v = *(const float2*)&x[(row0 + r) * F_IN + kw * 2];
        U32 whi, wlo;
        split2(v.x, v.y, whi, wlo);
        sAhi[r * 68 + kw] = whi;
        sAlo[r * 68 + kw] = wlo;
    }
    __syncthreads();

    float acc[2][2][4];
#pragma unroll
    for (int a = 0; a < 2; a++)
#pragma unroll
        for (int b = 0; b < 2; b++)
#pragma unroll
            for (int c = 0; c < 4; c++) acc[a][b][c] = 0.f;

#pragma unroll
    for (int kc = 0; kc < 8; kc++) {
        int kb = kc * 8 + cw;
        U32 ahi[2][4], alo[2][4];
#pragma unroll
        for (int mf = 0; mf < 2; mf++) {
            int r0i = wm * 32 + mf * 16 + rr, r8 = r0i + 8;
            ahi[mf][0] = sAhi[r0i * 68 + kb];     ahi[mf][1] = sAhi[r8 * 68 + kb];
            ahi[mf][2] = sAhi[r0i * 68 + kb + 4]; ahi[mf][3] = sAhi[r8 * 68 + kb + 4];
            alo[mf][0] = sAlo[r0i * 68 + kb];     alo[mf][1] = sAlo[r8 * 68 + kb];
            alo[mf][2] = sAlo[r0i * 68 + kb + 4]; alo[mf][3] = sAlo[r8 * 68 + kb + 4];
        }
#pragma unroll
        for (int nf = 0; nf < 2; nf++) {
            int nb = wn * 16 + nf * 8 + rr;
            U32 bh0 = sBhi[nb * 68 + kb], bh1 = sBhi[nb * 68 + kb + 4];
            U32 bl0 = sBlo[nb * 68 + kb], bl1 = sBlo[nb * 68 + kb + 4];
#pragma unroll
            for (int mf = 0; mf < 2; mf++) {
                mma16816(acc[mf][nf], ahi[mf], bh0, bh1);
                mma16816(acc[mf][nf], ahi[mf], bl0, bl1);
                mma16816(acc[mf][nf], alo[mf], bh0, bh1);
            }
        }
    }
#pragma unroll
    for (int mf = 0; mf < 2; mf++)
#pragma unroll
        for (int nf = 0; nf < 2; nf++) {
            int r = row0 + wm * 32 + mf * 16 + rr;
            int col = wn * 16 + nf * 8 + cw * 2;
            *(float2*)&g_h1[r * H1D + col]       = make_float2(acc[mf][nf][0], acc[mf][nf][1]);
            *(float2*)&g_h1[(r + 8) * H1D + col] = make_float2(acc[mf][nf][2], acc[mf][nf][3]);
        }
}

// ---------------- fused aggregation (both GCN hops), block per graph ---------
#define AGG_SMEM (131072 + 32768 + 2048 + 2048)
__global__ void __launch_bounds__(1024) aggf_kernel(const float* __restrict__ b1) {
    extern __shared__ char sm[];
    float2* sfeat = (float2*)sm;                              // 512 * 32 float2
    float2* sedge = (float2*)(sm + 131072);                   // 4096
    int*    scnt  = (int*)(sm + 131072 + 32768);              // 512
    int*    srp   = (int*)(sm + 131072 + 32768 + 2048);       // 512
    int b = blockIdx.x, t = threadIdx.x;
    int lane = t & 31, wid = t >> 5;
    int nbase = b * NPG;
    int ebase = b * EPG;

    float4* dst4 = (float4*)sfeat;
    {
        const float4* src = (const float4*)(g_h1 + (size_t)nbase * H1D);
#pragma unroll
        for (int i = 0; i < 8; i++) dst4[t + i * 1024] = src[t + i * 1024];
        const float4* esrc = (const float4*)(g_csre + ebase);
        float4* edst = (float4*)sedge;
#pragma unroll
        for (int i = 0; i < 2; i++) edst[t + i * 1024] = esrc[t + i * 1024];
        if (t < NPG) {
            scnt[t] = g_cnt[nbase + t];
            srp[t]  = g_rowptr[nbase + t] - ebase;
        }
    }
    __syncthreads();

    float2 bb = ((const float2*)b1)[lane];

    // phase 1: out1 = relu(Agg(h1) + b1)
    for (int n = wid; n < NPG; n += 32) {
        int c = scnt[n], st = srp[n];
        float di = rsqrtf((float)(c + 1));
        float d2 = di * di;
        float2 h = sfeat[n * 32 + lane];
        float ax = d2 * h.x, ay = d2 * h.y;
        int e = 0;
        for (; e + 1 < c; e += 2) {
            float2 e0 = sedge[st + e], e1 = sedge[st + e + 1];
            int s0 = __float_as_int(e0.x) & (NPG - 1);
            int s1 = __float_as_int(e1.x) & (NPG - 1);
            float2 p0 = sfeat[s0 * 32 + lane];
            float2 p1 = sfeat[s1 * 32 + lane];
            ax += e0.y * p0.x + e1.y * p1.x;
            ay += e0.y * p0.y + e1.y * p1.y;
        }
        if (e < c) {
            float2 e0 = sedge[st + e];
            int s0 = __float_as_int(e0.x) & (NPG - 1);
            float2 p0 = sfeat[s0 * 32 + lane];
            ax += e0.y * p0.x;
            ay += e0.y * p0.y;
        }
        ((float2*)g_out1)[(nbase + n) * 32 + lane] =
            make_float2(fmaxf(ax + bb.x, 0.f), fmaxf(ay + bb.y, 0.f));
    }
    __syncthreads();

    {
        const float4* src = (const float4*)(g_out1 + (size_t)nbase * H1D);
#pragma unroll
        for (int i = 0; i < 8; i++) dst4[t + i * 1024] = src[t + i * 1024];
    }
    __syncthreads();

    // phase 2: a2 = Agg(out1)
    for (int n = wid; n < NPG; n += 32) {
        int c = scnt[n], st = srp[n];
        float di = rsqrtf((float)(c + 1));
        float d2 = di * di;
        float2 h = sfeat[n * 32 + lane];
        float ax = d2 * h.x, ay = d2 * h.y;
        int e = 0;
        for (; e + 1 < c; e += 2) {
            float2 e0 = sedge[st + e], e1 = sedge[st + e + 1];
            int s0 = __float_as_int(e0.x) & (NPG - 1);
            int s1 = __float_as_int(e1.x) & (NPG - 1);
            float2 p0 = sfeat[s0 * 32 + lane];
            float2 p1 = sfeat[s1 * 32 + lane];
            ax += e0.y * p0.x + e1.y * p1.x;
            ay += e0.y * p0.y + e1.y * p1.y;
        }
        if (e < c) {
            float2 e0 = sedge[st + e];
            int s0 = __float_as_int(e0.x) & (NPG - 1);
            float2 p0 = sfeat[s0 * 32 + lane];
            ax += e0.y * p0.x;
            ay += e0.y * p0.y;
        }
        ((float2*)g_a2)[(nbase + n) * 32 + lane] = make_float2(ax, ay);
    }
}

// ---------------- GEMM 2: out2 = relu(a2 @ W2 + b2), single-stage smem -------
// A: 128 rows x 32 kwords, pitch 36. B: 128 n x 32 kwords, pitch 36.
__global__ void __launch_bounds__(512) gemm2_kernel(const float* __restrict__ W,
                                                    const float* __restrict__ b2) {
    __shared__ U32 sAhi[128 * 36], sAlo[128 * 36];
    __shared__ U32 sBhi[128 * 36], sBlo[128 * 36];
    int t = threadIdx.x;
    int warp = t >> 5, lane = t & 31;
    int wm = warp >> 2, wn = warp & 3;
    int rr = lane >> 2, cw = lane & 3;
    int row0 = blockIdx.x << 7;

    // stage B (W2): 128 n x 32 kwords
#pragma unroll
    for (int i = 0; i < 8; i++) {
        int w = t + (i << 9);
        int n = w >> 5, kw = w & 31;
        float v0 = W[(2 * kw) * H2D + n];
        float v1 = W[(2 * kw + 1) * H2D + n];
        U32 whi, wlo;
        split2(v0, v1, whi, wlo);
        sBhi[n * 36 + kw] = whi;
        sBlo[n * 36 + kw] = wlo;
    }
    // stage A (a2): 128 rows x 32 kwords
#pragma unroll
    for (int i = 0; i < 8; i++) {
        int w = t + (i << 9);
        int r = w >> 5, kw = w & 31;
        float2 v = *(const float2*)&g_a2[(row0 + r) * H1D + kw * 2];
        U32 whi, wlo;
        split2(v.x, v.y, whi, wlo);
        sAhi[r * 36 + kw] = whi;
        sAlo[r * 36 + kw] = wlo;
    }
    __syncthreads();

    float acc[2][4][4];
#pragma unroll
    for (int a = 0; a < 2; a++)
#pragma unroll
        for (int b = 0; b < 4; b++)
#pragma unroll
            for (int c = 0; c < 4; c++) acc[a][b][c] = 0.f;

#pragma unroll
    for (int kc = 0; kc < 4; kc++) {
        int kb = kc * 8 + cw;
        U32 ahi[2][4], alo[2][4];
#pragma unroll
        for (int mf = 0; mf < 2; mf++) {
            int r0i = wm * 32 + mf * 16 + rr, r8 = r0i + 8;
            ahi[mf][0] = sAhi[r0i * 36 + kb];     ahi[mf][1] = sAhi[r8 * 36 + kb];
            ahi[mf][2] = sAhi[r0i * 36 + kb + 4]; ahi[mf][3] = sAhi[r8 * 36 + kb + 4];
            alo[mf][0] = sAlo[r0i * 36 + kb];     alo[mf][1] = sAlo[r8 * 36 + kb];
            alo[mf][2] = sAlo[r0i * 36 + kb + 4]; alo[mf][3] = sAlo[r8 * 36 + kb + 4];
        }
#pragma unroll
        for (int nf = 0; nf < 4; nf++) {
            int nb = wn * 32 + nf * 8 + rr;
            U32 bh0 = sBhi[nb * 36 + kb], bh1 = sBhi[nb * 36 + kb + 4];
            U32 bl0 = sBlo[nb * 36 + kb], bl1 = sBlo[nb * 36 + kb + 4];
#pragma unroll
            for (int mf = 0; mf < 2; mf++) {
                mma16816(acc[mf][nf], ahi[mf], bh0, bh1);
                mma16816(acc[mf][nf], ahi[mf], bl0, bl1);
                mma16816(acc[mf][nf], alo[mf], bh0, bh1);
            }
        }
    }
#pragma unroll
    for (int mf = 0; mf < 2; mf++)
#pragma unroll
        for (int nf = 0; nf < 4; nf++) {
            int r = row0 + wm * 32 + mf * 16 + rr;
            int col = wn * 32 + nf * 8 + cw * 2;
            float bb0 = __ldg(&b2[col]), bb1 = __ldg(&b2[col + 1]);
            *(float2*)&g_out2[r * H2D + col] =
                make_float2(fmaxf(acc[mf][nf][0] + bb0, 0.f), fmaxf(acc[mf][nf][1] + bb1, 0.f));
            *(float2*)&g_out2[(r + 8) * H2D + col] =
                make_float2(fmaxf(acc[mf][nf][2] + bb0, 0.f), fmaxf(acc[mf][nf][3] + bb1, 0.f));
        }
}

// ---------------- per-graph: score, TopK sort, gated max pool, FC, softmax ---
__global__ void __launch_bounds__(512) final_kernel(const float* __restrict__ pw,
                                                    const float* __restrict__ fcW,
                                                    const float* __restrict__ fcb,
                                                    float* __restrict__ out) {
    __shared__ float skey[NPG];
    __shared__ int   sidx[NPG];
    __shared__ float partial[NPG];
    __shared__ float gfeat[H2D];
    __shared__ float logits[NCLS];
    __shared__ float s_lse;
    int b = blockIdx.x, t = threadIdx.x;
    int warp = t >> 5, lane = t & 31;
    const float* base = g_out2 + (size_t)b * NPG * H2D;

    {
        float4 pv = ((const float4*)pw)[lane];
        float nw = pv.x * pv.x + pv.y * pv.y + pv.z * pv.z + pv.w * pv.w;
#pragma unroll
        for (int o = 16; o > 0; o >>= 1) nw += __shfl_xor_sync(0xffffffffu, nw, o);
        float rnorm = rsqrtf(nw);
        for (int n = warp; n < NPG; n += 16) {
            float4 h = ((const float4*)(base + n * H2D))[lane];
            float d = h.x * pv.x + h.y * pv.y + h.z * pv.z + h.w * pv.w;
#pragma unroll
            for (int o = 16; o > 0; o >>= 1) d += __shfl_xor_sync(0xffffffffu, d, o);
            if (lane == 0) { skey[n] = d * rnorm; sidx[n] = n; }
        }
    }
    for (int k = 2; k <= NPG; k <<= 1) {
        for (int j = k >> 1; j > 0; j >>= 1) {
            __syncthreads();
            int ixj = t ^ j;
            if (ixj > t) {
                float ka = skey[t], kb = skey[ixj];
                int ia = sidx[t], ib = sidx[ixj];
                bool bGreater = (kb > ka) || (kb == ka && ib < ia);
                bool desc = ((t & k) == 0);
                if (desc == bGreater) {
                    skey[t] = kb; skey[ixj] = ka;
                    sidx[t] = ib; sidx[ixj] = ia;
                }
            }
        }
    }
    __syncthreads();
    float gate = (t < KSEL) ? tanhf(skey[t]) : 0.f;
    __syncthreads();
    if (t < KSEL) skey[t] = gate;
    __syncthreads();
    {
        int f = t & 127, part = t >> 7;
        float m = -3.4e38f;
#pragma unroll 4
        for (int kk = part; kk < KSEL; kk += 4) {
            int node = sidx[kk];
            m = fmaxf(m, base[node * H2D + f] * skey[kk]);
        }
        partial[t] = m;
    }
    __syncthreads();
    if (t < H2D)
        gfeat[t] = fmaxf(fmaxf(partial[t], partial[t + 128]),
                         fmaxf(partial[t + 256], partial[t + 384]));
    __syncthreads();
    if (t < NCLS * 32) {
        int c = t >> 5, ln = t & 31;
        float acc = 0.f;
        for (int f = ln; f < H2D; f += 32) acc += gfeat[f] * fcW[f * NCLS + c];
#pragma unroll
        for (int o = 16; o > 0; o >>= 1) acc += __shfl_down_sync(0xffffffffu, acc, o);
        if (ln == 0) logits[c] = acc + fcb[c];
    }
    __syncthreads();
    if (t == 0) {
        float mx = -3.4e38f;
        for (int c = 0; c < NCLS; c++) mx = fmaxf(mx, logits[c]);
        float s = 0.f;
        for (int c = 0; c < NCLS; c++) s += expf(logits[c] - mx);
        s_lse = mx + logf(s);
    }
    __syncthreads();
    if (t < NCLS) out[b * NCLS + t] = logits[t] - s_lse;
}

// ---------------- launch -----------------------------------------------------
extern "C" void kernel_launch(void* const* d_in, const int* in_sizes, int n_in,
                              void* d_out, int out_size) {
    const float* x    = (const float*)d_in[0];
    const int*   ei   = (const int*)d_in[1];
    const float* W1   = (const float*)d_in[3];
    const float* b1   = (const float*)d_in[4];
    const float* W2   = (const float*)d_in[5];
    const float* b2   = (const float*)d_in[6];
    const float* pw   = (const float*)d_in[7];
    const float* fcW  = (const float*)d_in[8];
    const float* fcb  = (const float*)d_in[9];
    float* out = (float*)d_out;

    cudaFuncSetAttribute(gemm1_kernel,
                         cudaFuncAttributeMaxDynamicSharedMemorySize, 0);
    cudaFuncSetAttribute(aggf_kernel,
                         cudaFuncAttributeMaxDynamicSharedMemorySize, AGG_SMEM);

    build_kernel<<<NGRAPH, 512>>>(ei);
    gemm1_kernel<<<NNODES / 128, 512>>>(x, W1);
    aggf_kernel<<<NGRAPH, 1024, AGG_SMEM>>>(b1);
    gemm2_kernel<<<NNODES / 128, 512>>>(W2, b2);
    final_kernel<<<NGRAPH, 512>>>(pw, fcW, fcb, out);
}

// round 16
// speedup vs baseline: 1.7933x; 1.3482x over previous
#include <cuda_runtime.h>
#include <cuda_bf16.h>

#define NNODES 65536
#define NEDGES 524288
#define NGRAPH 128
#define NPG    512
#define EPG    4096
#define F_IN   128
#define H1D    64
#define H2D    128
#define NCLS   10
#define KSEL   410

typedef unsigned int U32;

// ---------------- scratch (static device globals; no allocation) -------------
__device__ __align__(16) int    g_cnt[NNODES];
__device__ __align__(16) int    g_rowptr[NNODES];
__device__ __align__(16) float  g_dis[NNODES];
__device__ __align__(16) float2 g_csre[NEDGES];   // (bitcast src idx, edge weight)
__device__ __align__(16) float  g_h1[NNODES * H1D];
__device__ __align__(16) float  g_out1[NNODES * H1D];   // staging between agg phases
__device__ __align__(16) float  g_a2[NNODES * H1D];     // Agg(out1), pre-GEMM2
__device__ __align__(16) float  g_out2[NNODES * H2D];

// ---------------- helpers ----------------------------------------------------
__device__ __forceinline__ void split2(float vx, float vy, U32& whi, U32& wlo) {
    unsigned short h0 = __bfloat16_as_ushort(__float2bfloat16_rn(vx));
    unsigned short h1 = __bfloat16_as_ushort(__float2bfloat16_rn(vy));
    whi = (U32)h0 | ((U32)h1 << 16);
    float r0 = vx - __uint_as_float((U32)h0 << 16);
    float r1 = vy - __uint_as_float((U32)h1 << 16);
    unsigned short l0 = __bfloat16_as_ushort(__float2bfloat16_rn(r0));
    unsigned short l1 = __bfloat16_as_ushort(__float2bfloat16_rn(r1));
    wlo = (U32)l0 | ((U32)l1 << 16);
}

__device__ __forceinline__ void mma16816(float* c, const U32* a, U32 b0, U32 b1) {
    asm volatile(
        "mma.sync.aligned.m16n8k16.row.col.f32.bf16.bf16.f32 "
        "{%0,%1,%2,%3}, {%4,%5,%6,%7}, {%8,%9}, {%0,%1,%2,%3};"
        : "+f"(c[0]), "+f"(c[1]), "+f"(c[2]), "+f"(c[3])
        : "r"(a[0]), "r"(a[1]), "r"(a[2]), "r"(a[3]), "r"(b0), "r"(b1));
}

// ---------------- fused per-graph structure build ----------------------------
__global__ void __launch_bounds__(512) build_kernel(const int* __restrict__ ei) {
    __shared__ int   scnt[NPG];
    __shared__ int   sbase[NPG];
    __shared__ float sdis[NPG];
    __shared__ int   wsum[16];
    __shared__ int   sred;
    int b = blockIdx.x, t = threadIdx.x;
    int lane = t & 31, wid = t >> 5;
    int ebase = b * EPG;

    scnt[t] = 0;
    if (t == 0) sred = 0;
    __syncthreads();

    // int64 detect on this graph's src slice (node ids < 2^16)
    int v = 0;
    for (int i = t; i < EPG; i += 512) v |= ei[2 * (ebase + i) + 1];
#pragma unroll
    for (int o = 16; o > 0; o >>= 1) v |= __shfl_xor_sync(0xffffffffu, v, o);
    if (lane == 0 && v) atomicOr(&sred, 1);
    __syncthreads();
    bool is64 = (sred == 0);

    for (int i = t; i < EPG; i += 512) {
        int dv = is64 ? ei[2 * (NEDGES + ebase + i)] : ei[NEDGES + ebase + i];
        atomicAdd(&scnt[dv & (NPG - 1)], 1);
    }
    __syncthreads();
    int c = scnt[t];

    int inc = c;
#pragma unroll
    for (int o = 1; o < 32; o <<= 1) {
        int u = __shfl_up_sync(0xffffffffu, inc, o);
        if (lane >= o) inc += u;
    }
    if (lane == 31) wsum[wid] = inc;
    __syncthreads();
    if (wid == 0 && lane < 16) {
        int s = wsum[lane];
        int inc2 = s;
#pragma unroll
        for (int o = 1; o < 16; o <<= 1) {
            int u = __shfl_up_sync(0x0000ffffu, inc2, o);
            if (lane >= o) inc2 += u;
        }
        wsum[lane] = inc2 - s;
    }
    __syncthreads();
    int rp = ebase + (inc - c) + wsum[wid];

    int node = b * NPG + t;
    g_rowptr[node] = rp;
    g_cnt[node] = c;
    float dis = rsqrtf((float)(c + 1));
    g_dis[node] = dis;
    sbase[t] = rp;
    sdis[t] = dis;
    scnt[t] = 0;
    __syncthreads();

    for (int i = t; i < EPG; i += 512) {
        int sv, dv;
        if (is64) { sv = ei[2 * (ebase + i)]; dv = ei[2 * (NEDGES + ebase + i)]; }
        else      { sv = ei[ebase + i];       dv = ei[NEDGES + ebase + i]; }
        int dl = dv & (NPG - 1);
        int p = atomicAdd(&scnt[dl], 1);
        float w = sdis[sv & (NPG - 1)] * sdis[dl];
        g_csre[sbase[dl] + p] = make_float2(__int_as_float(sv), w);
    }
}

// ---------------- GEMM 1: h1 = x @ W1. 256 thr, tile 64x64, hi/lo uint2 ------
// warp grid 4m x 2n, warp tile 16x32. smem 69.6 KB -> 3 blocks/SM.
__global__ void __launch_bounds__(256) gemm1_kernel(const float* __restrict__ x,
                                                    const float* __restrict__ W) {
    __shared__ uint2 sA[64 * 68];   // [row][kword] (hi, lo); pitch 68
    __shared__ uint2 sB[64 * 68];   // [n][kword]
    int t = threadIdx.x;
    int warp = t >> 5, lane = t & 31;
    int wm = warp >> 1, wn = warp & 1;
    int rr = lane >> 2, cw = lane & 3;
    int row0 = blockIdx.x << 6;

    // stage B (W1): 64 n x 64 kwords
#pragma unroll
    for (int i = 0; i < 16; i++) {
        int w = t + (i << 8);
        int n = w & 63, kw = w >> 6;
        float v0 = W[(2 * kw) * H1D + n];
        float v1 = W[(2 * kw + 1) * H1D + n];
        U32 whi, wlo;
        split2(v0, v1, whi, wlo);
        sB[n * 68 + kw] = make_uint2(whi, wlo);
    }
    // stage A (x): 64 rows x 64 kwords
#pragma unroll
    for (int i = 0; i < 16; i++) {
        int w = t + (i << 8);
        int r = w >> 6, kw = w & 63;
        float2 v = *(const float2*)&x[(row0 + r) * F_IN + kw * 2];
        U32 whi, wlo;
        split2(v.x, v.y, whi, wlo);
        sA[r * 68 + kw] = make_uint2(whi, wlo);
    }
    __syncthreads();

    float acc[4][4];
#pragma unroll
    for (int a = 0; a < 4; a++)
#pragma unroll
        for (int c = 0; c < 4; c++) acc[a][c] = 0.f;

#pragma unroll
    for (int kc = 0; kc < 8; kc++) {
        int kb = kc * 8 + cw;
        int r0 = wm * 16 + rr, r8 = r0 + 8;
        uint2 a0 = sA[r0 * 68 + kb], a1 = sA[r8 * 68 + kb];
        uint2 a2 = sA[r0 * 68 + kb + 4], a3 = sA[r8 * 68 + kb + 4];
        U32 ahi[4] = {a0.x, a1.x, a2.x, a3.x};
        U32 alo[4] = {a0.y, a1.y, a2.y, a3.y};
#pragma unroll
        for (int nf = 0; nf < 4; nf++) {
            int nb = wn * 32 + nf * 8 + rr;
            uint2 b0 = sB[nb * 68 + kb], b1 = sB[nb * 68 + kb + 4];
            mma16816(acc[nf], ahi, b0.x, b1.x);
            mma16816(acc[nf], ahi, b0.y, b1.y);
            mma16816(acc[nf], alo, b0.x, b1.x);
        }
    }
#pragma unroll
    for (int nf = 0; nf < 4; nf++) {
        int r = row0 + wm * 16 + rr;
        int col = wn * 32 + nf * 8 + cw * 2;
        *(float2*)&g_h1[r * H1D + col]       = make_float2(acc[nf][0], acc[nf][1]);
        *(float2*)&g_h1[(r + 8) * H1D + col] = make_float2(acc[nf][2], acc[nf][3]);
    }
}

// ---------------- fused aggregation (both GCN hops), block per graph ---------
#define AGG_SMEM (131072 + 32768 + 2048 + 2048)
__global__ void __launch_bounds__(1024) aggf_kernel(const float* __restrict__ b1) {
    extern __shared__ char sm[];
    float2* sfeat = (float2*)sm;                              // 512 * 32 float2
    float2* sedge = (float2*)(sm + 131072);                   // 4096
    int*    scnt  = (int*)(sm + 131072 + 32768);              // 512
    int*    srp   = (int*)(sm + 131072 + 32768 + 2048);       // 512
    int b = blockIdx.x, t = threadIdx.x;
    int lane = t & 31, wid = t >> 5;
    int nbase = b * NPG;
    int ebase = b * EPG;

    float4* dst4 = (float4*)sfeat;
    {
        const float4* src = (const float4*)(g_h1 + (size_t)nbase * H1D);
#pragma unroll
        for (int i = 0; i < 8; i++) dst4[t + i * 1024] = src[t + i * 1024];
        const float4* esrc = (const float4*)(g_csre + ebase);
        float4* edst = (float4*)sedge;
#pragma unroll
        for (int i = 0; i < 2; i++) edst[t + i * 1024] = esrc[t + i * 1024];
        if (t < NPG) {
            scnt[t] = g_cnt[nbase + t];
            srp[t]  = g_rowptr[nbase + t] - ebase;
        }
    }
    __syncthreads();

    float2 bb = ((const float2*)b1)[lane];

    // phase 1: out1 = relu(Agg(h1) + b1)
    for (int n = wid; n < NPG; n += 32) {
        int c = scnt[n], st = srp[n];
        float di = rsqrtf((float)(c + 1));
        float d2 = di * di;
        float2 h = sfeat[n * 32 + lane];
        float ax = d2 * h.x, ay = d2 * h.y;
        int e = 0;
        for (; e + 1 < c; e += 2) {
            float2 e0 = sedge[st + e], e1 = sedge[st + e + 1];
            int s0 = __float_as_int(e0.x) & (NPG - 1);
            int s1 = __float_as_int(e1.x) & (NPG - 1);
            float2 p0 = sfeat[s0 * 32 + lane];
            float2 p1 = sfeat[s1 * 32 + lane];
            ax += e0.y * p0.x + e1.y * p1.x;
            ay += e0.y * p0.y + e1.y * p1.y;
        }
        if (e < c) {
            float2 e0 = sedge[st + e];
            int s0 = __float_as_int(e0.x) & (NPG - 1);
            float2 p0 = sfeat[s0 * 32 + lane];
            ax += e0.y * p0.x;
            ay += e0.y * p0.y;
        }
        ((float2*)g_out1)[(nbase + n) * 32 + lane] =
            make_float2(fmaxf(ax + bb.x, 0.f), fmaxf(ay + bb.y, 0.f));
    }
    __syncthreads();

    {
        const float4* src = (const float4*)(g_out1 + (size_t)nbase * H1D);
#pragma unroll
        for (int i = 0; i < 8; i++) dst4[t + i * 1024] = src[t + i * 1024];
    }
    __syncthreads();

    // phase 2: a2 = Agg(out1)
    for (int n = wid; n < NPG; n += 32) {
        int c = scnt[n], st = srp[n];
        float di = rsqrtf((float)(c + 1));
        float d2 = di * di;
        float2 h = sfeat[n * 32 + lane];
        float ax = d2 * h.x, ay = d2 * h.y;
        int e = 0;
        for (; e + 1 < c; e += 2) {
            float2 e0 = sedge[st + e], e1 = sedge[st + e + 1];
            int s0 = __float_as_int(e0.x) & (NPG - 1);
            int s1 = __float_as_int(e1.x) & (NPG - 1);
            float2 p0 = sfeat[s0 * 32 + lane];
            float2 p1 = sfeat[s1 * 32 + lane];
            ax += e0.y * p0.x + e1.y * p1.x;
            ay += e0.y * p0.y + e1.y * p1.y;
        }
        if (e < c) {
            float2 e0 = sedge[st + e];
            int s0 = __float_as_int(e0.x) & (NPG - 1);
            float2 p0 = sfeat[s0 * 32 + lane];
            ax += e0.y * p0.x;
            ay += e0.y * p0.y;
        }
        ((float2*)g_a2)[(nbase + n) * 32 + lane] = make_float2(ax, ay);
    }
}

// ---------------- GEMM 2: out2 = relu(a2 @ W2 + b2). 256 thr, tile 64x128 ----
// warp grid 2m x 4n, warp tile 32x32. smem 55.2 KB -> 3-4 blocks/SM.
__global__ void __launch_bounds__(256) gemm2_kernel(const float* __restrict__ W,
                                                    const float* __restrict__ b2) {
    __shared__ uint2 sA[64 * 36];    // [row][kword] (hi, lo); pitch 36
    __shared__ uint2 sB[128 * 36];   // [n][kword]
    int t = threadIdx.x;
    int warp = t >> 5, lane = t & 31;
    int wm = warp >> 2, wn = warp & 3;
    int rr = lane >> 2, cw = lane & 3;
    int row0 = blockIdx.x << 6;

    // stage B (W2): 128 n x 32 kwords
#pragma unroll
    for (int i = 0; i < 16; i++) {
        int w = t + (i << 8);
        int n = w & 127, kw = w >> 7;
        float v0 = W[(2 * kw) * H2D + n];
        float v1 = W[(2 * kw + 1) * H2D + n];
        U32 whi, wlo;
        split2(v0, v1, whi, wlo);
        sB[n * 36 + kw] = make_uint2(whi, wlo);
    }
    // stage A (a2): 64 rows x 32 kwords
#pragma unroll
    for (int i = 0; i < 8; i++) {
        int w = t + (i << 8);
        int r = w >> 5, kw = w & 31;
        float2 v = *(const float2*)&g_a2[(row0 + r) * H1D + kw * 2];
        U32 whi, wlo;
        split2(v.x, v.y, whi, wlo);
        sA[r * 36 + kw] = make_uint2(whi, wlo);
    }
    __syncthreads();

    float acc[2][4][4];
#pragma unroll
    for (int a = 0; a < 2; a++)
#pragma unroll
        for (int b = 0; b < 4; b++)
#pragma unroll
            for (int c = 0; c < 4; c++) acc[a][b][c] = 0.f;

#pragma unroll
    for (int kc = 0; kc < 4; kc++) {
        int kb = kc * 8 + cw;
        U32 ahi[2][4], alo[2][4];
#pragma unroll
        for (int mf = 0; mf < 2; mf++) {
            int r0 = wm * 32 + mf * 16 + rr, r8 = r0 + 8;
            uint2 a0 = sA[r0 * 36 + kb], a1 = sA[r8 * 36 + kb];
            uint2 a2 = sA[r0 * 36 + kb + 4], a3 = sA[r8 * 36 + kb + 4];
            ahi[mf][0] = a0.x; ahi[mf][1] = a1.x; ahi[mf][2] = a2.x; ahi[mf][3] = a3.x;
            alo[mf][0] = a0.y; alo[mf][1] = a1.y; alo[mf][2] = a2.y; alo[mf][3] = a3.y;
        }
#pragma unroll
        for (int nf = 0; nf < 4; nf++) {
            int nb = wn * 32 + nf * 8 + rr;
            uint2 b0 = sB[nb * 36 + kb], b1 = sB[nb * 36 + kb + 4];
#pragma unroll
            for (int mf = 0; mf < 2; mf++) {
                mma16816(acc[mf][nf], ahi[mf], b0.x, b1.x);
                mma16816(acc[mf][nf], ahi[mf], b0.y, b1.y);
                mma16816(acc[mf][nf], alo[mf], b0.x, b1.x);
            }
        }
    }
#pragma unroll
    for (int mf = 0; mf < 2; mf++)
#pragma unroll
        for (int nf = 0; nf < 4; nf++) {
            int r = row0 + wm * 32 + mf * 16 + rr;
            int col = wn * 32 + nf * 8 + cw * 2;
            float bb0 = __ldg(&b2[col]), bb1 = __ldg(&b2[col + 1]);
            *(float2*)&g_out2[r * H2D + col] =
                make_float2(fmaxf(acc[mf][nf][0] + bb0, 0.f), fmaxf(acc[mf][nf][1] + bb1, 0.f));
            *(float2*)&g_out2[(r + 8) * H2D + col] =
                make_float2(fmaxf(acc[mf][nf][2] + bb0, 0.f), fmaxf(acc[mf][nf][3] + bb1, 0.f));
        }
}

// ---------------- per-graph: score, TopK sort, gated max pool, FC, softmax ---
__global__ void __launch_bounds__(512) final_kernel(const float* __restrict__ pw,
                                                    const float* __restrict__ fcW,
                                                    const float* __restrict__ fcb,
                                                    float* __restrict__ out) {
    __shared__ float skey[NPG];
    __shared__ int   sidx[NPG];
    __shared__ float partial[NPG];
    __shared__ float gfeat[H2D];
    __shared__ float logits[NCLS];
    __shared__ float s_lse;
    int b = blockIdx.x, t = threadIdx.x;
    int warp = t >> 5, lane = t & 31;
    const float* base = g_out2 + (size_t)b * NPG * H2D;

    {
        float4 pv = ((const float4*)pw)[lane];
        float nw = pv.x * pv.x + pv.y * pv.y + pv.z * pv.z + pv.w * pv.w;
#pragma unroll
        for (int o = 16; o > 0; o >>= 1) nw += __shfl_xor_sync(0xffffffffu, nw, o);
        float rnorm = rsqrtf(nw);
        for (int n = warp; n < NPG; n += 16) {
            float4 h = ((const float4*)(base + n * H2D))[lane];
            float d = h.x * pv.x + h.y * pv.y + h.z * pv.z + h.w * pv.w;
#pragma unroll
            for (int o = 16; o > 0; o >>= 1) d += __shfl_xor_sync(0xffffffffu, d, o);
            if (lane == 0) { skey[n] = d * rnorm; sidx[n] = n; }
        }
    }
    for (int k = 2; k <= NPG; k <<= 1) {
        for (int j = k >> 1; j > 0; j >>= 1) {
            __syncthreads();
            int ixj = t ^ j;
            if (ixj > t) {
                float ka = skey[t], kb = skey[ixj];
                int ia = sidx[t], ib = sidx[ixj];
                bool bGreater = (kb > ka) || (kb == ka && ib < ia);
                bool desc = ((t & k) == 0);
                if (desc == bGreater) {
                    skey[t] = kb; skey[ixj] = ka;
                    sidx[t] = ib; sidx[ixj] = ia;
                }
            }
        }
    }
    __syncthreads();
    float gate = (t < KSEL) ? tanhf(skey[t]) : 0.f;
    __syncthreads();
    if (t < KSEL) skey[t] = gate;
    __syncthreads();
    {
        int f = t & 127, part = t >> 7;
        float m = -3.4e38f;
#pragma unroll 4
        for (int kk = part; kk < KSEL; kk += 4) {
            int node = sidx[kk];
            m = fmaxf(m, base[node * H2D + f] * skey[kk]);
        }
        partial[t] = m;
    }
    __syncthreads();
    if (t < H2D)
        gfeat[t] = fmaxf(fmaxf(partial[t], partial[t + 128]),
                         fmaxf(partial[t + 256], partial[t + 384]));
    __syncthreads();
    if (t < NCLS * 32) {
        int c = t >> 5, ln = t & 31;
        float acc = 0.f;
        for (int f = ln; f < H2D; f += 32) acc += gfeat[f] * fcW[f * NCLS + c];
#pragma unroll
        for (int o = 16; o > 0; o >>= 1) acc += __shfl_down_sync(0xffffffffu, acc, o);
        if (ln == 0) logits[c] = acc + fcb[c];
    }
    __syncthreads();
    if (t == 0) {
        float mx = -3.4e38f;
        for (int c = 0; c < NCLS; c++) mx = fmaxf(mx, logits[c]);
        float s = 0.f;
        for (int c = 0; c < NCLS; c++) s += expf(logits[c] - mx);
        s_lse = mx + logf(s);
    }
    __syncthreads();
    if (t < NCLS) out[b * NCLS + t] = logits[t] - s_lse;
}

// ---------------- launch -----------------------------------------------------
extern "C" void kernel_launch(void* const* d_in, const int* in_sizes, int n_in,
                              void* d_out, int out_size) {
    const float* x    = (const float*)d_in[0];
    const int*   ei   = (const int*)d_in[1];
    const float* W1   = (const float*)d_in[3];
    const float* b1   = (const float*)d_in[4];
    const float* W2   = (const float*)d_in[5];
    const float* b2   = (const float*)d_in[6];
    const float* pw   = (const float*)d_in[7];
    const float* fcW  = (const float*)d_in[8];
    const float* fcb  = (const float*)d_in[9];
    float* out = (float*)d_out;

    cudaFuncSetAttribute(aggf_kernel,
                         cudaFuncAttributeMaxDynamicSharedMemorySize, AGG_SMEM);

    build_kernel<<<NGRAPH, 512>>>(ei);
    gemm1_kernel<<<NNODES / 64, 256>>>(x, W1);
    aggf_kernel<<<NGRAPH, 1024, AGG_SMEM>>>(b1);
    gemm2_kernel<<<NNODES / 64, 256>>>(W2, b2);
    final_kernel<<<NGRAPH, 512>>>(pw, fcW, fcb, out);
}